// round 5
// baseline (speedup 1.0000x reference)
#include <cuda_runtime.h>

#define NN 100000
#define DD 128
#define EE 1600000
#define HH 4
#define NBLK 391   // ceil(NN/256)

typedef unsigned long long u64;

__device__ __forceinline__ u64 fma2(u64 a, u64 b, u64 c) {
    u64 d; asm("fma.rn.f32x2 %0,%1,%2,%3;" : "=l"(d) : "l"(a), "l"(b), "l"(c));
    return d;
}
__device__ __forceinline__ u64 mul2(u64 a, u64 b) {
    u64 d; asm("mul.rn.f32x2 %0,%1,%2;" : "=l"(d) : "l"(a), "l"(b));
    return d;
}
__device__ __forceinline__ u64 add2(u64 a, u64 b) {
    u64 d; asm("add.rn.f32x2 %0,%1,%2;" : "=l"(d) : "l"(a), "l"(b));
    return d;
}
__device__ __forceinline__ u64 pack2(float lo, float hi) {
    u64 d; asm("mov.b64 %0,{%1,%2};" : "=l"(d) : "f"(lo), "f"(hi));
    return d;
}
__device__ __forceinline__ float2 unpack2(u64 v) {
    float lo, hi; asm("mov.b64 {%0,%1},%2;" : "=f"(lo), "=f"(hi) : "l"(v));
    return make_float2(lo, hi);
}

// ---- scratch (__device__ globals per allocation-free rule) ----
__device__ float g_xl[(size_t)NN * DD];   // x @ W_l
__device__ float g_xr[(size_t)NN * DD];   // x @ W_r
__device__ int   g_srcs[EE];              // dst-sorted edge sources
__device__ int   g_cnt[NN];               // per-dst degree
__device__ int   g_off[NN + 1];           // CSR offsets
__device__ int   g_cur[NN];               // scatter cursors
__device__ int   g_bsum[512];             // block sums for scan
__device__ int   g_is64;

// ---------------------------------------------------------------------------
__global__ void k_zero() {
    for (int i = blockIdx.x * blockDim.x + threadIdx.x; i < NN;
         i += gridDim.x * blockDim.x)
        g_cnt[i] = 0;
}

__global__ void k_detect(const int* __restrict__ ei_raw) {
    int all_zero = 1;
    for (int k = 0; k < 128; k++)
        if (ei_raw[2 * k + 1] != 0) { all_zero = 0; break; }
    g_is64 = all_zero;
}

// histogram of dst, directly from raw buffer
__global__ void k_hist(const void* __restrict__ ei_raw, int E) {
    int is64 = g_is64;
    const long long* e64 = (const long long*)ei_raw;
    const int*       e32 = (const int*)ei_raw;
    for (int e = blockIdx.x * blockDim.x + threadIdx.x; e < E;
         e += gridDim.x * blockDim.x) {
        int d = is64 ? (int)e64[E + e] : e32[E + e];
        d = min(max(d, 0), NN - 1);
        atomicAdd(&g_cnt[d], 1);
    }
}

// ---- 2-level exclusive scan of g_cnt -> g_off ----
__global__ void k_scan1() {
    __shared__ int s[256];
    int t = threadIdx.x;
    int i = blockIdx.x * 256 + t;
    int v = (i < NN) ? g_cnt[i] : 0;
    s[t] = v;
    __syncthreads();
#pragma unroll
    for (int d = 1; d < 256; d <<= 1) {
        int add = (t >= d) ? s[t - d] : 0;
        __syncthreads();
        s[t] += add;
        __syncthreads();
    }
    if (i < NN) g_off[i] = s[t] - v;
    if (t == 255) g_bsum[blockIdx.x] = s[255];
}

__global__ void k_scan2(int E) {
    __shared__ int s[512];
    int t = threadIdx.x;
    int v = (t < NBLK) ? g_bsum[t] : 0;
    s[t] = v;
    __syncthreads();
#pragma unroll
    for (int d = 1; d < 512; d <<= 1) {
        int add = (t >= d) ? s[t - d] : 0;
        __syncthreads();
        s[t] += add;
        __syncthreads();
    }
    if (t < NBLK) g_bsum[t] = s[t] - v;
    if (t == 0) g_off[NN] = E;
}

__global__ void k_scan3() {
    for (int i = blockIdx.x * blockDim.x + threadIdx.x; i < NN;
         i += gridDim.x * blockDim.x) {
        int o = g_off[i] + g_bsum[i >> 8];
        g_off[i] = o;
        g_cur[i] = o;
    }
}

__global__ void k_scatter(const void* __restrict__ ei_raw, int E) {
    int is64 = g_is64;
    const long long* e64 = (const long long*)ei_raw;
    const int*       e32 = (const int*)ei_raw;
    for (int e = blockIdx.x * blockDim.x + threadIdx.x; e < E;
         e += gridDim.x * blockDim.x) {
        int s, d;
        if (is64) { s = (int)e64[e]; d = (int)e64[E + e]; }
        else      { s = e32[e];      d = e32[E + e]; }
        s = min(max(s, 0), NN - 1);
        d = min(max(d, 0), NN - 1);
        int pos = atomicAdd(&g_cur[d], 1);
        g_srcs[pos] = s;
    }
}

// ---------------------------------------------------------------------------
// fused dual GEMM with packed f32x2 FMA: xl = x@Wl, xr = x@Wr.
// 8 warps x 8 rows = 64 rows/block; thread owns 4 output cols per matrix.
// ---------------------------------------------------------------------------
__global__ __launch_bounds__(256, 2)
void k_gemm(const float* __restrict__ x,
            const float* __restrict__ Wl,
            const float* __restrict__ Wr, int n) {
    __shared__ float sWl[32 * 128];
    __shared__ float sWr[32 * 128];
    int tid  = threadIdx.x;
    int lane = tid & 31;
    int warp = tid >> 5;
    int row0 = blockIdx.x * 64 + warp * 8;

    u64 accL[8][2] = {};
    u64 accR[8][2] = {};

    for (int k0 = 0; k0 < 128; k0 += 32) {
        const float4* wl4 = (const float4*)(Wl + k0 * 128);
        const float4* wr4 = (const float4*)(Wr + k0 * 128);
#pragma unroll
        for (int j = 0; j < 4; j++) {
            ((float4*)sWl)[tid + 256 * j] = wl4[tid + 256 * j];
            ((float4*)sWr)[tid + 256 * j] = wr4[tid + 256 * j];
        }
        __syncthreads();

        float xv[8];
#pragma unroll
        for (int r = 0; r < 8; r++) {
            int row = row0 + r;
            xv[r] = (row < n) ? x[(size_t)row * 128 + k0 + lane] : 0.f;
        }

#pragma unroll 4
        for (int kk = 0; kk < 32; kk++) {
            float4 wl = ((const float4*)sWl)[kk * 32 + lane];
            float4 wr = ((const float4*)sWr)[kk * 32 + lane];
            u64 wl01 = pack2(wl.x, wl.y), wl23 = pack2(wl.z, wl.w);
            u64 wr01 = pack2(wr.x, wr.y), wr23 = pack2(wr.z, wr.w);
#pragma unroll
            for (int r = 0; r < 8; r++) {
                float xb = __shfl_sync(0xffffffffu, xv[r], kk);
                u64 xb2 = pack2(xb, xb);
                accL[r][0] = fma2(xb2, wl01, accL[r][0]);
                accL[r][1] = fma2(xb2, wl23, accL[r][1]);
                accR[r][0] = fma2(xb2, wr01, accR[r][0]);
                accR[r][1] = fma2(xb2, wr23, accR[r][1]);
            }
        }
        __syncthreads();
    }

#pragma unroll
    for (int r = 0; r < 8; r++) {
        int row = row0 + r;
        if (row < n) {
            float2 l01 = unpack2(accL[r][0]), l23 = unpack2(accL[r][1]);
            float2 r01 = unpack2(accR[r][0]), r23 = unpack2(accR[r][1]);
            ((float4*)(g_xl + (size_t)row * 128))[lane] =
                make_float4(l01.x, l01.y, l23.x, l23.y);
            ((float4*)(g_xr + (size_t)row * 128))[lane] =
                make_float4(r01.x, r01.y, r23.x, r23.y);
        }
    }
}

// ---------------------------------------------------------------------------
// fused score + softmax + aggregate: one warp per node, single pass.
// a*leakyrelu(v) == (0.6a)*v + (0.4a)*|v|  (exact for slope 0.2),
// all channel math in packed f32x2; exp on 4 leader lanes only.
// ---------------------------------------------------------------------------
__global__ void k_fused(float* __restrict__ out,
                        const float* __restrict__ att,
                        const float* __restrict__ bias, int n) {
    int node = (blockIdx.x * blockDim.x + threadIdx.x) >> 5;
    int lane = threadIdx.x & 31;
    if (node >= n) return;

    const u64 ABSM = 0x7FFFFFFF7FFFFFFFULL;
    float4 a4 = ((const float4*)att)[lane];
    u64 c1_01 = pack2(0.6f * a4.x, 0.6f * a4.y);
    u64 c1_23 = pack2(0.6f * a4.z, 0.6f * a4.w);
    u64 c2_01 = pack2(0.4f * a4.x, 0.4f * a4.y);
    u64 c2_23 = pack2(0.4f * a4.z, 0.4f * a4.w);

    float4 xi = ((const float4*)(g_xr + (size_t)node * 128))[lane];
    u64 xi01 = pack2(xi.x, xi.y), xi23 = pack2(xi.z, xi.w);

    int beg = g_off[node];
    int end = g_off[node + 1];
    int lead = lane & 24;

    u64 acc01 = 0, acc23 = 0;
    float den = 0.f;

    int p = beg;
    for (; p + 1 < end; p += 2) {
        int s0 = g_srcs[p], s1 = g_srcs[p + 1];
        float4 x0 = ((const float4*)(g_xl + (size_t)s0 * 128))[lane];
        float4 x1 = ((const float4*)(g_xl + (size_t)s1 * 128))[lane];
        u64 xj0a = pack2(x0.x, x0.y), xj0b = pack2(x0.z, x0.w);
        u64 xj1a = pack2(x1.x, x1.y), xj1b = pack2(x1.z, x1.w);

        u64 v0a = add2(xi01, xj0a), v0b = add2(xi23, xj0b);
        u64 v1a = add2(xi01, xj1a), v1b = add2(xi23, xj1b);
        u64 sA2 = mul2(c1_01, v0a);
        u64 sB2 = mul2(c1_01, v1a);
        sA2 = fma2(c1_23, v0b, sA2);
        sB2 = fma2(c1_23, v1b, sB2);
        sA2 = fma2(c2_01, v0a & ABSM, sA2);
        sB2 = fma2(c2_01, v1a & ABSM, sB2);
        sA2 = fma2(c2_23, v0b & ABSM, sA2);
        sB2 = fma2(c2_23, v1b & ABSM, sB2);
        float2 fA = unpack2(sA2), fB = unpack2(sB2);
        float sA = fA.x + fA.y, sB = fB.x + fB.y;

        sA += __shfl_down_sync(0xffffffffu, sA, 4, 8);
        sB += __shfl_down_sync(0xffffffffu, sB, 4, 8);
        sA += __shfl_down_sync(0xffffffffu, sA, 2, 8);
        sB += __shfl_down_sync(0xffffffffu, sB, 2, 8);
        sA += __shfl_down_sync(0xffffffffu, sA, 1, 8);
        sB += __shfl_down_sync(0xffffffffu, sB, 1, 8);

        float exA, exB;
        if ((lane & 7) == 0) { exA = __expf(sA); exB = __expf(sB); }
        exA = __shfl_sync(0xffffffffu, exA, lead);
        exB = __shfl_sync(0xffffffffu, exB, lead);

        den += exA + exB;
        u64 eA2 = pack2(exA, exA), eB2 = pack2(exB, exB);
        acc01 = fma2(eA2, xj0a, acc01);
        acc23 = fma2(eA2, xj0b, acc23);
        acc01 = fma2(eB2, xj1a, acc01);
        acc23 = fma2(eB2, xj1b, acc23);
    }
    if (p < end) {
        int s0 = g_srcs[p];
        float4 x0 = ((const float4*)(g_xl + (size_t)s0 * 128))[lane];
        u64 xj0a = pack2(x0.x, x0.y), xj0b = pack2(x0.z, x0.w);
        u64 v0a = add2(xi01, xj0a), v0b = add2(xi23, xj0b);
        u64 sA2 = mul2(c1_01, v0a);
        sA2 = fma2(c1_23, v0b, sA2);
        sA2 = fma2(c2_01, v0a & ABSM, sA2);
        sA2 = fma2(c2_23, v0b & ABSM, sA2);
        float2 fA = unpack2(sA2);
        float sA = fA.x + fA.y;
        sA += __shfl_down_sync(0xffffffffu, sA, 4, 8);
        sA += __shfl_down_sync(0xffffffffu, sA, 2, 8);
        sA += __shfl_down_sync(0xffffffffu, sA, 1, 8);
        float exA;
        if ((lane & 7) == 0) exA = __expf(sA);
        exA = __shfl_sync(0xffffffffu, exA, lead);
        den += exA;
        u64 eA2 = pack2(exA, exA);
        acc01 = fma2(eA2, xj0a, acc01);
        acc23 = fma2(eA2, xj0b, acc23);
    }

    float invd = 1.f / (den + 1e-16f);
    float2 a01 = unpack2(acc01), a23 = unpack2(acc23);
    float4 b4 = ((const float4*)bias)[lane];
    float4 o;
    o.x = fmaf(a01.x, invd, b4.x);
    o.y = fmaf(a01.y, invd, b4.y);
    o.z = fmaf(a23.x, invd, b4.z);
    o.w = fmaf(a23.y, invd, b4.w);
    ((float4*)(out + (size_t)node * 128))[lane] = o;
}

extern "C" void kernel_launch(void* const* d_in, const int* in_sizes, int n_in,
                              void* d_out, int out_size) {
    const float* x    = (const float*)d_in[0];
    const void*  ei   = d_in[1];
    const float* Wl   = (const float*)d_in[2];
    const float* Wr   = (const float*)d_in[3];
    const float* att  = (const float*)d_in[4];
    const float* bias = (const float*)d_in[5];
    float*       out  = (float*)d_out;

    int n = in_sizes[0] / DD;   // 100000
    int E = in_sizes[1] / 2;    // 1600000

    k_zero   <<<256, 256>>>();
    k_detect <<<1, 1>>>((const int*)ei);
    k_hist   <<<2048, 256>>>(ei, E);
    k_scan1  <<<NBLK, 256>>>();
    k_scan2  <<<1, 512>>>(E);
    k_scan3  <<<256, 256>>>();
    k_scatter<<<2048, 256>>>(ei, E);
    k_gemm   <<<(n + 63) / 64, 256>>>(x, Wl, Wr, n);
    k_fused  <<<(n * 32 + 255) / 256, 256>>>(out, att, bias, n);
}

// round 6
// speedup vs baseline: 1.0445x; 1.0445x over previous
#include <cuda_runtime.h>

#define NN 100000
#define DD 128
#define EE 1600000
#define HH 4
#define NBLK 391   // ceil(NN/256)

// ---- scratch (__device__ globals per allocation-free rule) ----
__device__ float g_xl[(size_t)NN * DD];   // x @ W_l
__device__ float g_xr[(size_t)NN * DD];   // x @ W_r
__device__ int   g_srcs[EE];              // dst-sorted edge sources
__device__ int   g_cnt[NN];               // per-dst degree
__device__ int   g_off[NN + 1];           // CSR offsets
__device__ int   g_cur[NN];               // scatter cursors
__device__ int   g_bsum[512];             // block sums for scan
__device__ int   g_is64;

// ---------------------------------------------------------------------------
// K0: zero degree counters + detect edge dtype (int64 vs int32) in one launch.
// ---------------------------------------------------------------------------
__global__ void k_zero(const int* __restrict__ ei_raw) {
    if (blockIdx.x == 0 && threadIdx.x == 0) {
        int all_zero = 1;
        for (int k = 0; k < 128; k++)
            if (ei_raw[2 * k + 1] != 0) { all_zero = 0; break; }
        g_is64 = all_zero;
    }
    for (int i = blockIdx.x * blockDim.x + threadIdx.x; i < NN;
         i += gridDim.x * blockDim.x)
        g_cnt[i] = 0;
}

// histogram of dst, directly from raw buffer
__global__ void k_hist(const void* __restrict__ ei_raw, int E) {
    int is64 = g_is64;
    const long long* e64 = (const long long*)ei_raw;
    const int*       e32 = (const int*)ei_raw;
    for (int e = blockIdx.x * blockDim.x + threadIdx.x; e < E;
         e += gridDim.x * blockDim.x) {
        int d = is64 ? (int)e64[E + e] : e32[E + e];
        d = min(max(d, 0), NN - 1);
        atomicAdd(&g_cnt[d], 1);
    }
}

// ---- 2-level exclusive scan of g_cnt -> g_off ----
__global__ void k_scan1() {
    __shared__ int s[256];
    int t = threadIdx.x;
    int i = blockIdx.x * 256 + t;
    int v = (i < NN) ? g_cnt[i] : 0;
    s[t] = v;
    __syncthreads();
#pragma unroll
    for (int d = 1; d < 256; d <<= 1) {
        int add = (t >= d) ? s[t - d] : 0;
        __syncthreads();
        s[t] += add;
        __syncthreads();
    }
    if (i < NN) g_off[i] = s[t] - v;
    if (t == 255) g_bsum[blockIdx.x] = s[255];
}

__global__ void k_scan2(int E) {
    __shared__ int s[512];
    int t = threadIdx.x;
    int v = (t < NBLK) ? g_bsum[t] : 0;
    s[t] = v;
    __syncthreads();
#pragma unroll
    for (int d = 1; d < 512; d <<= 1) {
        int add = (t >= d) ? s[t - d] : 0;
        __syncthreads();
        s[t] += add;
        __syncthreads();
    }
    if (t < NBLK) g_bsum[t] = s[t] - v;
    if (t == 0) g_off[NN] = E;
}

__global__ void k_scan3() {
    for (int i = blockIdx.x * blockDim.x + threadIdx.x; i < NN;
         i += gridDim.x * blockDim.x) {
        int o = g_off[i] + g_bsum[i >> 8];
        g_off[i] = o;
        g_cur[i] = o;
    }
}

__global__ void k_scatter(const void* __restrict__ ei_raw, int E) {
    int is64 = g_is64;
    const long long* e64 = (const long long*)ei_raw;
    const int*       e32 = (const int*)ei_raw;
    for (int e = blockIdx.x * blockDim.x + threadIdx.x; e < E;
         e += gridDim.x * blockDim.x) {
        int s, d;
        if (is64) { s = (int)e64[e]; d = (int)e64[E + e]; }
        else      { s = e32[e];      d = e32[E + e]; }
        s = min(max(s, 0), NN - 1);
        d = min(max(d, 0), NN - 1);
        int pos = atomicAdd(&g_cur[d], 1);
        g_srcs[pos] = s;
    }
}

// ---------------------------------------------------------------------------
// fused dual GEMM (R4-proven): xl = x@Wl, xr = x@Wr.
// 8 warps x 8 rows = 64 rows/block; thread owns 4 output cols per matrix.
// ---------------------------------------------------------------------------
__global__ __launch_bounds__(256, 2)
void k_gemm(const float* __restrict__ x,
            const float* __restrict__ Wl,
            const float* __restrict__ Wr, int n) {
    __shared__ float sWl[32 * 128];
    __shared__ float sWr[32 * 128];
    int tid  = threadIdx.x;
    int lane = tid & 31;
    int warp = tid >> 5;
    int row0 = blockIdx.x * 64 + warp * 8;

    float accL[8][4] = {};
    float accR[8][4] = {};

    for (int k0 = 0; k0 < 128; k0 += 32) {
        const float4* wl4 = (const float4*)(Wl + k0 * 128);
        const float4* wr4 = (const float4*)(Wr + k0 * 128);
#pragma unroll
        for (int j = 0; j < 4; j++) {
            ((float4*)sWl)[tid + 256 * j] = wl4[tid + 256 * j];
            ((float4*)sWr)[tid + 256 * j] = wr4[tid + 256 * j];
        }
        __syncthreads();

        float xv[8];
#pragma unroll
        for (int r = 0; r < 8; r++) {
            int row = row0 + r;
            xv[r] = (row < n) ? x[(size_t)row * 128 + k0 + lane] : 0.f;
        }

#pragma unroll 4
        for (int kk = 0; kk < 32; kk++) {
            float4 wl = ((const float4*)sWl)[kk * 32 + lane];
            float4 wr = ((const float4*)sWr)[kk * 32 + lane];
#pragma unroll
            for (int r = 0; r < 8; r++) {
                float xb = __shfl_sync(0xffffffffu, xv[r], kk);
                accL[r][0] = fmaf(xb, wl.x, accL[r][0]);
                accL[r][1] = fmaf(xb, wl.y, accL[r][1]);
                accL[r][2] = fmaf(xb, wl.z, accL[r][2]);
                accL[r][3] = fmaf(xb, wl.w, accL[r][3]);
                accR[r][0] = fmaf(xb, wr.x, accR[r][0]);
                accR[r][1] = fmaf(xb, wr.y, accR[r][1]);
                accR[r][2] = fmaf(xb, wr.z, accR[r][2]);
                accR[r][3] = fmaf(xb, wr.w, accR[r][3]);
            }
        }
        __syncthreads();
    }

#pragma unroll
    for (int r = 0; r < 8; r++) {
        int row = row0 + r;
        if (row < n) {
            ((float4*)(g_xl + (size_t)row * 128))[lane] =
                make_float4(accL[r][0], accL[r][1], accL[r][2], accL[r][3]);
            ((float4*)(g_xr + (size_t)row * 128))[lane] =
                make_float4(accR[r][0], accR[r][1], accR[r][2], accR[r][3]);
        }
    }
}

// ---------------------------------------------------------------------------
// fused score + softmax + aggregate: one warp per node, single pass,
// 4-edge unroll for memory-level parallelism against L2 latency.
// a*leakyrelu(v) == (0.6a)*v + (0.4a)*|v| (exact for slope 0.2); |v| is a
// free SASS operand modifier. exp on 4 leader lanes only.
// ---------------------------------------------------------------------------
__global__ void k_fused(float* __restrict__ out,
                        const float* __restrict__ att,
                        const float* __restrict__ bias, int n) {
    int node = (blockIdx.x * blockDim.x + threadIdx.x) >> 5;
    int lane = threadIdx.x & 31;
    if (node >= n) return;

    float4 a4 = ((const float4*)att)[lane];
    float c1x = 0.6f * a4.x, c1y = 0.6f * a4.y, c1z = 0.6f * a4.z, c1w = 0.6f * a4.w;
    float c2x = 0.4f * a4.x, c2y = 0.4f * a4.y, c2z = 0.4f * a4.z, c2w = 0.4f * a4.w;

    float4 xi = ((const float4*)(g_xr + (size_t)node * 128))[lane];
    int beg = g_off[node];
    int end = g_off[node + 1];
    int lead = lane & 24;  // 8-lane group leader

    float4 acc = make_float4(0.f, 0.f, 0.f, 0.f);
    float den = 0.f;

    int p = beg;
    for (; p + 3 < end; p += 4) {
        int   si[4];
        float4 xj[4];
#pragma unroll
        for (int u = 0; u < 4; u++) si[u] = g_srcs[p + u];
#pragma unroll
        for (int u = 0; u < 4; u++)
            xj[u] = ((const float4*)(g_xl + (size_t)si[u] * 128))[lane];

        float sc[4];
#pragma unroll
        for (int u = 0; u < 4; u++) {
            float v, s;
            v = xi.x + xj[u].x; s  = c1x * v; s = fmaf(c2x, fabsf(v), s);
            v = xi.y + xj[u].y; s = fmaf(c1y, v, s); s = fmaf(c2y, fabsf(v), s);
            v = xi.z + xj[u].z; s = fmaf(c1z, v, s); s = fmaf(c2z, fabsf(v), s);
            v = xi.w + xj[u].w; s = fmaf(c1w, v, s); s = fmaf(c2w, fabsf(v), s);
            sc[u] = s;
        }
#pragma unroll
        for (int u = 0; u < 4; u++) sc[u] += __shfl_down_sync(0xffffffffu, sc[u], 4, 8);
#pragma unroll
        for (int u = 0; u < 4; u++) sc[u] += __shfl_down_sync(0xffffffffu, sc[u], 2, 8);
#pragma unroll
        for (int u = 0; u < 4; u++) sc[u] += __shfl_down_sync(0xffffffffu, sc[u], 1, 8);

        float ex[4];
        if ((lane & 7) == 0) {
#pragma unroll
            for (int u = 0; u < 4; u++) ex[u] = __expf(sc[u]);
        }
#pragma unroll
        for (int u = 0; u < 4; u++) ex[u] = __shfl_sync(0xffffffffu, ex[u], lead);

#pragma unroll
        for (int u = 0; u < 4; u++) {
            den += ex[u];
            acc.x = fmaf(ex[u], xj[u].x, acc.x);
            acc.y = fmaf(ex[u], xj[u].y, acc.y);
            acc.z = fmaf(ex[u], xj[u].z, acc.z);
            acc.w = fmaf(ex[u], xj[u].w, acc.w);
        }
    }
    for (; p < end; p++) {
        int s0 = g_srcs[p];
        float4 xj0 = ((const float4*)(g_xl + (size_t)s0 * 128))[lane];
        float v, s;
        v = xi.x + xj0.x; s  = c1x * v; s = fmaf(c2x, fabsf(v), s);
        v = xi.y + xj0.y; s = fmaf(c1y, v, s); s = fmaf(c2y, fabsf(v), s);
        v = xi.z + xj0.z; s = fmaf(c1z, v, s); s = fmaf(c2z, fabsf(v), s);
        v = xi.w + xj0.w; s = fmaf(c1w, v, s); s = fmaf(c2w, fabsf(v), s);
        s += __shfl_down_sync(0xffffffffu, s, 4, 8);
        s += __shfl_down_sync(0xffffffffu, s, 2, 8);
        s += __shfl_down_sync(0xffffffffu, s, 1, 8);
        float ex0;
        if ((lane & 7) == 0) ex0 = __expf(s);
        ex0 = __shfl_sync(0xffffffffu, ex0, lead);
        den += ex0;
        acc.x = fmaf(ex0, xj0.x, acc.x);
        acc.y = fmaf(ex0, xj0.y, acc.y);
        acc.z = fmaf(ex0, xj0.z, acc.z);
        acc.w = fmaf(ex0, xj0.w, acc.w);
    }

    float invd = 1.f / (den + 1e-16f);
    float4 b4 = ((const float4*)bias)[lane];
    float4 o;
    o.x = fmaf(acc.x, invd, b4.x);
    o.y = fmaf(acc.y, invd, b4.y);
    o.z = fmaf(acc.z, invd, b4.z);
    o.w = fmaf(acc.w, invd, b4.w);
    ((float4*)(out + (size_t)node * 128))[lane] = o;
}

extern "C" void kernel_launch(void* const* d_in, const int* in_sizes, int n_in,
                              void* d_out, int out_size) {
    const float* x    = (const float*)d_in[0];
    const void*  ei   = d_in[1];
    const float* Wl   = (const float*)d_in[2];
    const float* Wr   = (const float*)d_in[3];
    const float* att  = (const float*)d_in[4];
    const float* bias = (const float*)d_in[5];
    float*       out  = (float*)d_out;

    int n = in_sizes[0] / DD;   // 100000
    int E = in_sizes[1] / 2;    // 1600000

    k_zero   <<<256, 256>>>((const int*)ei);
    k_hist   <<<2048, 256>>>(ei, E);
    k_scan1  <<<NBLK, 256>>>();
    k_scan2  <<<1, 512>>>(E);
    k_scan3  <<<256, 256>>>();
    k_scatter<<<2048, 256>>>(ei, E);
    k_gemm   <<<(n + 63) / 64, 256>>>(x, Wl, Wr, n);
    k_fused  <<<(n * 32 + 255) / 256, 256>>>(out, att, bias, n);
}

// round 7
// speedup vs baseline: 1.0520x; 1.0072x over previous
#include <cuda_runtime.h>

#define NN 100000
#define DD 128
#define EE 1600000
#define HH 4
#define NBLK 391   // ceil(NN/256)

// ---- scratch (__device__ globals per allocation-free rule) ----
__device__ float g_xl[(size_t)NN * DD];   // x @ W_l  (HOT: random-gathered 16x)
__device__ float g_xr[(size_t)NN * DD];   // x @ W_r  (streamed once)
__device__ int   g_srcs[EE];              // dst-sorted edge sources
__device__ int   g_cnt[NN];               // per-dst degree
__device__ int   g_off[NN + 1];           // CSR offsets
__device__ int   g_cur[NN];               // scatter cursors
__device__ int   g_bsum[512];             // block sums for scan
__device__ int   g_is64;

// ---------------------------------------------------------------------------
// K0: zero degree counters + detect edge dtype (int64 vs int32).
// ---------------------------------------------------------------------------
__global__ void k_zero(const int* __restrict__ ei_raw) {
    if (blockIdx.x == 0 && threadIdx.x == 0) {
        int all_zero = 1;
        for (int k = 0; k < 128; k++)
            if (ei_raw[2 * k + 1] != 0) { all_zero = 0; break; }
        g_is64 = all_zero;
    }
    for (int i = blockIdx.x * blockDim.x + threadIdx.x; i < NN;
         i += gridDim.x * blockDim.x)
        g_cnt[i] = 0;
}

// histogram of dst, directly from raw buffer (streaming reads)
__global__ void k_hist(const void* __restrict__ ei_raw, int E) {
    int is64 = g_is64;
    const long long* e64 = (const long long*)ei_raw;
    const int*       e32 = (const int*)ei_raw;
    for (int e = blockIdx.x * blockDim.x + threadIdx.x; e < E;
         e += gridDim.x * blockDim.x) {
        int d = is64 ? (int)__ldcs(&e64[E + e]) : __ldcs(&e32[E + e]);
        d = min(max(d, 0), NN - 1);
        atomicAdd(&g_cnt[d], 1);
    }
}

// ---- 2-level exclusive scan of g_cnt -> g_off ----
__global__ void k_scan1() {
    __shared__ int s[256];
    int t = threadIdx.x;
    int i = blockIdx.x * 256 + t;
    int v = (i < NN) ? g_cnt[i] : 0;
    s[t] = v;
    __syncthreads();
#pragma unroll
    for (int d = 1; d < 256; d <<= 1) {
        int add = (t >= d) ? s[t - d] : 0;
        __syncthreads();
        s[t] += add;
        __syncthreads();
    }
    if (i < NN) g_off[i] = s[t] - v;
    if (t == 255) g_bsum[blockIdx.x] = s[255];
}

__global__ void k_scan2(int E) {
    __shared__ int s[512];
    int t = threadIdx.x;
    int v = (t < NBLK) ? g_bsum[t] : 0;
    s[t] = v;
    __syncthreads();
#pragma unroll
    for (int d = 1; d < 512; d <<= 1) {
        int add = (t >= d) ? s[t - d] : 0;
        __syncthreads();
        s[t] += add;
        __syncthreads();
    }
    if (t < NBLK) g_bsum[t] = s[t] - v;
    if (t == 0) g_off[NN] = E;
}

__global__ void k_scan3() {
    for (int i = blockIdx.x * blockDim.x + threadIdx.x; i < NN;
         i += gridDim.x * blockDim.x) {
        int o = g_off[i] + g_bsum[i >> 8];
        g_off[i] = o;
        g_cur[i] = o;
    }
}

__global__ void k_scatter(const void* __restrict__ ei_raw, int E) {
    int is64 = g_is64;
    const long long* e64 = (const long long*)ei_raw;
    const int*       e32 = (const int*)ei_raw;
    for (int e = blockIdx.x * blockDim.x + threadIdx.x; e < E;
         e += gridDim.x * blockDim.x) {
        int s, d;
        if (is64) { s = (int)__ldcs(&e64[e]); d = (int)__ldcs(&e64[E + e]); }
        else      { s = __ldcs(&e32[e]);      d = __ldcs(&e32[E + e]); }
        s = min(max(s, 0), NN - 1);
        d = min(max(d, 0), NN - 1);
        int pos = atomicAdd(&g_cur[d], 1);
        __stcs(&g_srcs[pos], s);
    }
}

// ---------------------------------------------------------------------------
// fused dual GEMM: xl = x@Wl, xr = x@Wr. 8 warps x 8 rows = 64 rows/block.
// xr stored evict-first (streamed once later); xl stored default (hot).
// ---------------------------------------------------------------------------
__global__ __launch_bounds__(256, 2)
void k_gemm(const float* __restrict__ x,
            const float* __restrict__ Wl,
            const float* __restrict__ Wr, int n) {
    __shared__ float sWl[32 * 128];
    __shared__ float sWr[32 * 128];
    int tid  = threadIdx.x;
    int lane = tid & 31;
    int warp = tid >> 5;
    int row0 = blockIdx.x * 64 + warp * 8;

    float accL[8][4] = {};
    float accR[8][4] = {};

    for (int k0 = 0; k0 < 128; k0 += 32) {
        const float4* wl4 = (const float4*)(Wl + k0 * 128);
        const float4* wr4 = (const float4*)(Wr + k0 * 128);
#pragma unroll
        for (int j = 0; j < 4; j++) {
            ((float4*)sWl)[tid + 256 * j] = wl4[tid + 256 * j];
            ((float4*)sWr)[tid + 256 * j] = wr4[tid + 256 * j];
        }
        __syncthreads();

        float xv[8];
#pragma unroll
        for (int r = 0; r < 8; r++) {
            int row = row0 + r;
            xv[r] = (row < n) ? __ldcs(&x[(size_t)row * 128 + k0 + lane]) : 0.f;
        }

#pragma unroll 4
        for (int kk = 0; kk < 32; kk++) {
            float4 wl = ((const float4*)sWl)[kk * 32 + lane];
            float4 wr = ((const float4*)sWr)[kk * 32 + lane];
#pragma unroll
            for (int r = 0; r < 8; r++) {
                float xb = __shfl_sync(0xffffffffu, xv[r], kk);
                accL[r][0] = fmaf(xb, wl.x, accL[r][0]);
                accL[r][1] = fmaf(xb, wl.y, accL[r][1]);
                accL[r][2] = fmaf(xb, wl.z, accL[r][2]);
                accL[r][3] = fmaf(xb, wl.w, accL[r][3]);
                accR[r][0] = fmaf(xb, wr.x, accR[r][0]);
                accR[r][1] = fmaf(xb, wr.y, accR[r][1]);
                accR[r][2] = fmaf(xb, wr.z, accR[r][2]);
                accR[r][3] = fmaf(xb, wr.w, accR[r][3]);
            }
        }
        __syncthreads();
    }

#pragma unroll
    for (int r = 0; r < 8; r++) {
        int row = row0 + r;
        if (row < n) {
            ((float4*)(g_xl + (size_t)row * 128))[lane] =
                make_float4(accL[r][0], accL[r][1], accL[r][2], accL[r][3]);
            __stcs(&((float4*)(g_xr + (size_t)row * 128))[lane],
                   make_float4(accR[r][0], accR[r][1], accR[r][2], accR[r][3]));
        }
    }
}

// ---------------------------------------------------------------------------
// fused score + softmax + aggregate: one warp per node, single pass.
// Streaming data (xr row, g_srcs, out) uses evict-first hints so the
// random xl gathers stay L2-resident.
// ---------------------------------------------------------------------------
__global__ void k_fused(float* __restrict__ out,
                        const float* __restrict__ att,
                        const float* __restrict__ bias, int n) {
    int node = (blockIdx.x * blockDim.x + threadIdx.x) >> 5;
    int lane = threadIdx.x & 31;
    if (node >= n) return;

    float4 a4 = ((const float4*)att)[lane];
    float c1x = 0.6f * a4.x, c1y = 0.6f * a4.y, c1z = 0.6f * a4.z, c1w = 0.6f * a4.w;
    float c2x = 0.4f * a4.x, c2y = 0.4f * a4.y, c2z = 0.4f * a4.z, c2w = 0.4f * a4.w;

    float4 xi = __ldcs(&((const float4*)(g_xr + (size_t)node * 128))[lane]);
    int beg = g_off[node];
    int end = g_off[node + 1];
    int lead = lane & 24;  // 8-lane group leader

    float4 acc = make_float4(0.f, 0.f, 0.f, 0.f);
    float den = 0.f;

    int p = beg;
    for (; p + 3 < end; p += 4) {
        int   si[4];
        float4 xj[4];
#pragma unroll
        for (int u = 0; u < 4; u++) si[u] = __ldcs(&g_srcs[p + u]);
#pragma unroll
        for (int u = 0; u < 4; u++)
            xj[u] = __ldg(&((const float4*)(g_xl + (size_t)si[u] * 128))[lane]);

        float sc[4];
#pragma unroll
        for (int u = 0; u < 4; u++) {
            float v, s;
            v = xi.x + xj[u].x; s  = c1x * v; s = fmaf(c2x, fabsf(v), s);
            v = xi.y + xj[u].y; s = fmaf(c1y, v, s); s = fmaf(c2y, fabsf(v), s);
            v = xi.z + xj[u].z; s = fmaf(c1z, v, s); s = fmaf(c2z, fabsf(v), s);
            v = xi.w + xj[u].w; s = fmaf(c1w, v, s); s = fmaf(c2w, fabsf(v), s);
            sc[u] = s;
        }
#pragma unroll
        for (int u = 0; u < 4; u++) sc[u] += __shfl_down_sync(0xffffffffu, sc[u], 4, 8);
#pragma unroll
        for (int u = 0; u < 4; u++) sc[u] += __shfl_down_sync(0xffffffffu, sc[u], 2, 8);
#pragma unroll
        for (int u = 0; u < 4; u++) sc[u] += __shfl_down_sync(0xffffffffu, sc[u], 1, 8);

        float ex[4];
        if ((lane & 7) == 0) {
#pragma unroll
            for (int u = 0; u < 4; u++) ex[u] = __expf(sc[u]);
        }
#pragma unroll
        for (int u = 0; u < 4; u++) ex[u] = __shfl_sync(0xffffffffu, ex[u], lead);

#pragma unroll
        for (int u = 0; u < 4; u++) {
            den += ex[u];
            acc.x = fmaf(ex[u], xj[u].x, acc.x);
            acc.y = fmaf(ex[u], xj[u].y, acc.y);
            acc.z = fmaf(ex[u], xj[u].z, acc.z);
            acc.w = fmaf(ex[u], xj[u].w, acc.w);
        }
    }
    for (; p < end; p++) {
        int s0 = __ldcs(&g_srcs[p]);
        float4 xj0 = __ldg(&((const float4*)(g_xl + (size_t)s0 * 128))[lane]);
        float v, s;
        v = xi.x + xj0.x; s  = c1x * v; s = fmaf(c2x, fabsf(v), s);
        v = xi.y + xj0.y; s = fmaf(c1y, v, s); s = fmaf(c2y, fabsf(v), s);
        v = xi.z + xj0.z; s = fmaf(c1z, v, s); s = fmaf(c2z, fabsf(v), s);
        v = xi.w + xj0.w; s = fmaf(c1w, v, s); s = fmaf(c2w, fabsf(v), s);
        s += __shfl_down_sync(0xffffffffu, s, 4, 8);
        s += __shfl_down_sync(0xffffffffu, s, 2, 8);
        s += __shfl_down_sync(0xffffffffu, s, 1, 8);
        float ex0;
        if ((lane & 7) == 0) ex0 = __expf(s);
        ex0 = __shfl_sync(0xffffffffu, ex0, lead);
        den += ex0;
        acc.x = fmaf(ex0, xj0.x, acc.x);
        acc.y = fmaf(ex0, xj0.y, acc.y);
        acc.z = fmaf(ex0, xj0.z, acc.z);
        acc.w = fmaf(ex0, xj0.w, acc.w);
    }

    float invd = 1.f / (den + 1e-16f);
    float4 b4 = ((const float4*)bias)[lane];
    float4 o;
    o.x = fmaf(acc.x, invd, b4.x);
    o.y = fmaf(acc.y, invd, b4.y);
    o.z = fmaf(acc.z, invd, b4.z);
    o.w = fmaf(acc.w, invd, b4.w);
    __stcs(&((float4*)(out + (size_t)node * 128))[lane], o);
}

extern "C" void kernel_launch(void* const* d_in, const int* in_sizes, int n_in,
                              void* d_out, int out_size) {
    const float* x    = (const float*)d_in[0];
    const void*  ei   = d_in[1];
    const float* Wl   = (const float*)d_in[2];
    const float* Wr   = (const float*)d_in[3];
    const float* att  = (const float*)d_in[4];
    const float* bias = (const float*)d_in[5];
    float*       out  = (float*)d_out;

    int n = in_sizes[0] / DD;   // 100000
    int E = in_sizes[1] / 2;    // 1600000

    // k_gemm placed at launch index 3 so ncu (which samples launch #3)
    // profiles it; gemm has no dependency on the scan chain.
    k_zero   <<<256, 256>>>((const int*)ei);
    k_hist   <<<2048, 256>>>(ei, E);
    k_scan1  <<<NBLK, 256>>>();
    k_gemm   <<<(n + 63) / 64, 256>>>(x, Wl, Wr, n);
    k_scan2  <<<1, 512>>>(E);
    k_scan3  <<<256, 256>>>();
    k_scatter<<<2048, 256>>>(ei, E);
    k_fused  <<<(n * 32 + 255) / 256, 256>>>(out, att, bias, n);
}

// round 9
// speedup vs baseline: 1.1991x; 1.1399x over previous
#include <cuda_runtime.h>

#define NN 100000
#define DD 128
#define EE 1600000
#define NBLK 391   // ceil(NN/256)

// ---- scratch (__device__ globals per allocation-free rule) ----
__device__ float g_xl[(size_t)NN * DD];   // x @ W_l (hot: gathered 16x)
__device__ float g_xr[(size_t)NN * DD];   // x @ W_r (streamed once)
__device__ int   g_srcs[EE];
__device__ int   g_cnt[NN];
__device__ int   g_off[NN + 1];
__device__ int   g_cur[NN];
__device__ int   g_bsum[512];
__device__ int   g_is64;
// W pre-split to tf32 hi/lo, layout [k][n] with n in 0..255 = [Wl | Wr] cols
__device__ float g_w_hi[128 * 256];
__device__ float g_w_lo[128 * 256];

__device__ __forceinline__ float f2tf(float f) {
    unsigned u;
    asm("cvt.rna.tf32.f32 %0,%1;" : "=r"(u) : "f"(f));
    return __uint_as_float(u);
}
__device__ __forceinline__ void mma_tf32(float* c, const float* a,
                                         float b0, float b1) {
    asm volatile(
        "mma.sync.aligned.m16n8k8.row.col.f32.tf32.tf32.f32 "
        "{%0,%1,%2,%3}, {%4,%5,%6,%7}, {%8,%9}, {%0,%1,%2,%3};"
        : "+f"(c[0]), "+f"(c[1]), "+f"(c[2]), "+f"(c[3])
        : "r"(__float_as_uint(a[0])), "r"(__float_as_uint(a[1])),
          "r"(__float_as_uint(a[2])), "r"(__float_as_uint(a[3])),
          "r"(__float_as_uint(b0)), "r"(__float_as_uint(b1)));
}

// ---------------------------------------------------------------------------
// K0: zero degree counters + detect edge dtype (int64 vs int32).
// ---------------------------------------------------------------------------
__global__ void k_zero(const int* __restrict__ ei_raw) {
    if (blockIdx.x == 0 && threadIdx.x == 0) {
        int all_zero = 1;
        for (int k = 0; k < 128; k++)
            if (ei_raw[2 * k + 1] != 0) { all_zero = 0; break; }
        g_is64 = all_zero;
    }
    for (int i = blockIdx.x * blockDim.x + threadIdx.x; i < NN;
         i += gridDim.x * blockDim.x)
        g_cnt[i] = 0;
}

__global__ void k_hist(const void* __restrict__ ei_raw, int E) {
    int is64 = g_is64;
    const long long* e64 = (const long long*)ei_raw;
    const int*       e32 = (const int*)ei_raw;
    for (int e = blockIdx.x * blockDim.x + threadIdx.x; e < E;
         e += gridDim.x * blockDim.x) {
        int d = is64 ? (int)__ldcs(&e64[E + e]) : __ldcs(&e32[E + e]);
        d = min(max(d, 0), NN - 1);
        atomicAdd(&g_cnt[d], 1);
    }
}

// ---------------------------------------------------------------------------
// pre-split W -> tf32 hi/lo, [k][n] layout (n: 0..127 Wl, 128..255 Wr)
// ---------------------------------------------------------------------------
__global__ void k_prepw(const float* __restrict__ Wl,
                        const float* __restrict__ Wr) {
    int i = blockIdx.x * 256 + threadIdx.x;  // 32768 = 128*256
    int k = i >> 8, nc = i & 255;
    float w = (nc < 128) ? Wl[k * 128 + nc] : Wr[k * 128 + (nc - 128)];
    float hi = f2tf(w);
    g_w_hi[i] = hi;
    g_w_lo[i] = f2tf(w - hi);
}

// ---------------------------------------------------------------------------
// tensor-core dual GEMM via mma.sync tf32 (split hi/lo for fp32-like accuracy)
// block: 256 thr / 8 warps; tile M=64 x N=256; warp M32 x N64; K chunks of 8.
// ---------------------------------------------------------------------------
#define SA_STR 12    // conflict-free A row stride (words)
#define SB_STR 264   // conflict-free B row stride (words)

__global__ __launch_bounds__(256, 2)
void k_tc(const float* __restrict__ x, int n) {
    __shared__ float sAh[64 * SA_STR], sAl[64 * SA_STR];
    __shared__ float sBh[8 * SB_STR], sBl[8 * SB_STR];

    int tid  = threadIdx.x;
    int lane = tid & 31;
    int wid  = tid >> 5;
    int row0   = blockIdx.x * 64;
    int mrow0  = (wid & 1) * 32;       // warp row offset in tile
    int ncol0  = (wid >> 1) * 64;      // warp col offset in tile (0..192)

    // staging indices
    int arow = tid >> 2;               // 0..63
    int akq  = tid & 3;                // k-pair 0..3 (k = akq*2, akq*2+1)
    int bk0  = tid >> 6;               // 0..3  (first float4: k rows 0..3)
    int bn0  = (tid & 63) * 4;         // n offset

    float acc[2][8][4] = {};

    // prologue: load chunk 0 into regs
    float2 av;
    float4 bh0, bh1, bl0, bl1;
    {
        size_t xrow = (size_t)(row0 + arow);
        if (row0 + arow < n)
            av = *(const float2*)(x + xrow * 128 + akq * 2);
        else
            av = make_float2(0.f, 0.f);
        bh0 = *(const float4*)(g_w_hi + (size_t)bk0 * 256 + bn0);
        bh1 = *(const float4*)(g_w_hi + (size_t)(bk0 + 4) * 256 + bn0);
        bl0 = *(const float4*)(g_w_lo + (size_t)bk0 * 256 + bn0);
        bl1 = *(const float4*)(g_w_lo + (size_t)(bk0 + 4) * 256 + bn0);
    }

    for (int kc = 0; kc < 16; kc++) {
        __syncthreads();   // previous compute done reading smem
        // store staged chunk
        {
            float h0 = f2tf(av.x), h1 = f2tf(av.y);
            float l0 = f2tf(av.x - h0), l1 = f2tf(av.y - h1);
            *(float2*)(sAh + arow * SA_STR + akq * 2) = make_float2(h0, h1);
            *(float2*)(sAl + arow * SA_STR + akq * 2) = make_float2(l0, l1);
            *(float4*)(sBh + bk0 * SB_STR + bn0)       = bh0;
            *(float4*)(sBh + (bk0 + 4) * SB_STR + bn0) = bh1;
            *(float4*)(sBl + bk0 * SB_STR + bn0)       = bl0;
            *(float4*)(sBl + (bk0 + 4) * SB_STR + bn0) = bl1;
        }
        __syncthreads();
        // prefetch next chunk (latency covered by compute)
        if (kc < 15) {
            int kn = (kc + 1) * 8;
            if (row0 + arow < n)
                av = *(const float2*)(x + (size_t)(row0 + arow) * 128 + kn + akq * 2);
            bh0 = *(const float4*)(g_w_hi + (size_t)(kn + bk0) * 256 + bn0);
            bh1 = *(const float4*)(g_w_hi + (size_t)(kn + bk0 + 4) * 256 + bn0);
            bl0 = *(const float4*)(g_w_lo + (size_t)(kn + bk0) * 256 + bn0);
            bl1 = *(const float4*)(g_w_lo + (size_t)(kn + bk0 + 4) * 256 + bn0);
        }
        // compute chunk: A frags (hi/lo) for 2 m-chunks, then 8 n-chunks
        float ah[2][4], al[2][4];
#pragma unroll
        for (int m = 0; m < 2; m++) {
            int r  = mrow0 + m * 16 + (lane >> 2);
            int kk = lane & 3;
            ah[m][0] = sAh[r * SA_STR + kk];
            ah[m][1] = sAh[(r + 8) * SA_STR + kk];
            ah[m][2] = sAh[r * SA_STR + kk + 4];
            ah[m][3] = sAh[(r + 8) * SA_STR + kk + 4];
            al[m][0] = sAl[r * SA_STR + kk];
            al[m][1] = sAl[(r + 8) * SA_STR + kk];
            al[m][2] = sAl[r * SA_STR + kk + 4];
            al[m][3] = sAl[(r + 8) * SA_STR + kk + 4];
        }
#pragma unroll
        for (int j = 0; j < 8; j++) {
            int nb = ncol0 + j * 8 + (lane >> 2);
            int kk = lane & 3;
            float b_h0 = sBh[kk * SB_STR + nb];
            float b_h1 = sBh[(kk + 4) * SB_STR + nb];
            float b_l0 = sBl[kk * SB_STR + nb];
            float b_l1 = sBl[(kk + 4) * SB_STR + nb];
#pragma unroll
            for (int m = 0; m < 2; m++) {
                mma_tf32(acc[m][j], ah[m], b_h0, b_h1);
                mma_tf32(acc[m][j], ah[m], b_l0, b_l1);
                mma_tf32(acc[m][j], al[m], b_h0, b_h1);
            }
        }
    }

    // epilogue: C frag c0: (row, 2c) c1: (row, 2c+1) c2/c3: row+8
#pragma unroll
    for (int m = 0; m < 2; m++) {
        int row  = row0 + mrow0 + m * 16 + (lane >> 2);
        int row8 = row + 8;
#pragma unroll
        for (int j = 0; j < 8; j++) {
            int col = ncol0 + j * 8 + 2 * (lane & 3);
            float* mat = (col < 128) ? g_xl : g_xr;
            int cc = col & 127;
            if (row < n)
                *(float2*)(mat + (size_t)row * 128 + cc) =
                    make_float2(acc[m][j][0], acc[m][j][1]);
            if (row8 < n)
                *(float2*)(mat + (size_t)row8 * 128 + cc) =
                    make_float2(acc[m][j][2], acc[m][j][3]);
        }
    }
}

// ---- 2-level exclusive scan of g_cnt -> g_off ----
__global__ void k_scan1() {
    __shared__ int s[256];
    int t = threadIdx.x;
    int i = blockIdx.x * 256 + t;
    int v = (i < NN) ? g_cnt[i] : 0;
    s[t] = v;
    __syncthreads();
#pragma unroll
    for (int d = 1; d < 256; d <<= 1) {
        int add = (t >= d) ? s[t - d] : 0;
        __syncthreads();
        s[t] += add;
        __syncthreads();
    }
    if (i < NN) g_off[i] = s[t] - v;
    if (t == 255) g_bsum[blockIdx.x] = s[255];
}

__global__ void k_scan2(int E) {
    __shared__ int s[512];
    int t = threadIdx.x;
    int v = (t < NBLK) ? g_bsum[t] : 0;
    s[t] = v;
    __syncthreads();
#pragma unroll
    for (int d = 1; d < 512; d <<= 1) {
        int add = (t >= d) ? s[t - d] : 0;
        __syncthreads();
        s[t] += add;
        __syncthreads();
    }
    if (t < NBLK) g_bsum[t] = s[t] - v;
    if (t == 0) g_off[NN] = E;
}

__global__ void k_scan3() {
    for (int i = blockIdx.x * blockDim.x + threadIdx.x; i < NN;
         i += gridDim.x * blockDim.x) {
        int o = g_off[i] + g_bsum[i >> 8];
        g_off[i] = o;
        g_cur[i] = o;
    }
}

__global__ void k_scatter(const void* __restrict__ ei_raw, int E) {
    int is64 = g_is64;
    const long long* e64 = (const long long*)ei_raw;
    const int*       e32 = (const int*)ei_raw;
    for (int e = blockIdx.x * blockDim.x + threadIdx.x; e < E;
         e += gridDim.x * blockDim.x) {
        int s, d;
        if (is64) { s = (int)__ldcs(&e64[e]); d = (int)__ldcs(&e64[E + e]); }
        else      { s = __ldcs(&e32[e]);      d = __ldcs(&e32[E + e]); }
        s = min(max(s, 0), NN - 1);
        d = min(max(d, 0), NN - 1);
        int pos = atomicAdd(&g_cur[d], 1);
        __stcs(&g_srcs[pos], s);
    }
}

// ---------------------------------------------------------------------------
// fused score + softmax + aggregate (proven): one warp per node, single pass.
// ---------------------------------------------------------------------------
__global__ void k_fused(float* __restrict__ out,
                        const float* __restrict__ att,
                        const float* __restrict__ bias, int n) {
    int node = (blockIdx.x * blockDim.x + threadIdx.x) >> 5;
    int lane = threadIdx.x & 31;
    if (node >= n) return;

    float4 a4 = ((const float4*)att)[lane];
    float c1x = 0.6f * a4.x, c1y = 0.6f * a4.y, c1z = 0.6f * a4.z, c1w = 0.6f * a4.w;
    float c2x = 0.4f * a4.x, c2y = 0.4f * a4.y, c2z = 0.4f * a4.z, c2w = 0.4f * a4.w;

    float4 xi = __ldcs(&((const float4*)(g_xr + (size_t)node * 128))[lane]);
    int beg = g_off[node];
    int end = g_off[node + 1];
    int lead = lane & 24;

    float4 acc = make_float4(0.f, 0.f, 0.f, 0.f);
    float den = 0.f;

    int p = beg;
    for (; p + 3 < end; p += 4) {
        int   si[4];
        float4 xj[4];
#pragma unroll
        for (int u = 0; u < 4; u++) si[u] = __ldcs(&g_srcs[p + u]);
#pragma unroll
        for (int u = 0; u < 4; u++)
            xj[u] = __ldg(&((const float4*)(g_xl + (size_t)si[u] * 128))[lane]);

        float sc[4];
#pragma unroll
        for (int u = 0; u < 4; u++) {
            float v, s;
            v = xi.x + xj[u].x; s  = c1x * v; s = fmaf(c2x, fabsf(v), s);
            v = xi.y + xj[u].y; s = fmaf(c1y, v, s); s = fmaf(c2y, fabsf(v), s);
            v = xi.z + xj[u].z; s = fmaf(c1z, v, s); s = fmaf(c2z, fabsf(v), s);
            v = xi.w + xj[u].w; s = fmaf(c1w, v, s); s = fmaf(c2w, fabsf(v), s);
            sc[u] = s;
        }
#pragma unroll
        for (int u = 0; u < 4; u++) sc[u] += __shfl_down_sync(0xffffffffu, sc[u], 4, 8);
#pragma unroll
        for (int u = 0; u < 4; u++) sc[u] += __shfl_down_sync(0xffffffffu, sc[u], 2, 8);
#pragma unroll
        for (int u = 0; u < 4; u++) sc[u] += __shfl_down_sync(0xffffffffu, sc[u], 1, 8);

        float ex[4];
        if ((lane & 7) == 0) {
#pragma unroll
            for (int u = 0; u < 4; u++) ex[u] = __expf(sc[u]);
        }
#pragma unroll
        for (int u = 0; u < 4; u++) ex[u] = __shfl_sync(0xffffffffu, ex[u], lead);

#pragma unroll
        for (int u = 0; u < 4; u++) {
            den += ex[u];
            acc.x = fmaf(ex[u], xj[u].x, acc.x);
            acc.y = fmaf(ex[u], xj[u].y, acc.y);
            acc.z = fmaf(ex[u], xj[u].z, acc.z);
            acc.w = fmaf(ex[u], xj[u].w, acc.w);
        }
    }
    for (; p < end; p++) {
        int s0 = __ldcs(&g_srcs[p]);
        float4 xj0 = __ldg(&((const float4*)(g_xl + (size_t)s0 * 128))[lane]);
        float v, s;
        v = xi.x + xj0.x; s  = c1x * v; s = fmaf(c2x, fabsf(v), s);
        v = xi.y + xj0.y; s = fmaf(c1y, v, s); s = fmaf(c2y, fabsf(v), s);
        v = xi.z + xj0.z; s = fmaf(c1z, v, s); s = fmaf(c2z, fabsf(v), s);
        v = xi.w + xj0.w; s = fmaf(c1w, v, s); s = fmaf(c2w, fabsf(v), s);
        s += __shfl_down_sync(0xffffffffu, s, 4, 8);
        s += __shfl_down_sync(0xffffffffu, s, 2, 8);
        s += __shfl_down_sync(0xffffffffu, s, 1, 8);
        float ex0;
        if ((lane & 7) == 0) ex0 = __expf(s);
        ex0 = __shfl_sync(0xffffffffu, ex0, lead);
        den += ex0;
        acc.x = fmaf(ex0, xj0.x, acc.x);
        acc.y = fmaf(ex0, xj0.y, acc.y);
        acc.z = fmaf(ex0, xj0.z, acc.z);
        acc.w = fmaf(ex0, xj0.w, acc.w);
    }

    float invd = 1.f / (den + 1e-16f);
    float4 b4 = ((const float4*)bias)[lane];
    float4 o;
    o.x = fmaf(acc.x, invd, b4.x);
    o.y = fmaf(acc.y, invd, b4.y);
    o.z = fmaf(acc.z, invd, b4.z);
    o.w = fmaf(acc.w, invd, b4.w);
    __stcs(&((float4*)(out + (size_t)node * 128))[lane], o);
}

extern "C" void kernel_launch(void* const* d_in, const int* in_sizes, int n_in,
                              void* d_out, int out_size) {
    const float* x    = (const float*)d_in[0];
    const void*  ei   = d_in[1];
    const float* Wl   = (const float*)d_in[2];
    const float* Wr   = (const float*)d_in[3];
    const float* att  = (const float*)d_in[4];
    const float* bias = (const float*)d_in[5];
    float*       out  = (float*)d_out;

    int n = in_sizes[0] / DD;   // 100000
    int E = in_sizes[1] / 2;    // 1600000

    // k_tc at launch index 3 (ncu samples launch #3)
    k_zero   <<<256, 256>>>((const int*)ei);
    k_hist   <<<2048, 256>>>(ei, E);
    k_prepw  <<<128, 256>>>(Wl, Wr);
    k_tc     <<<(n + 63) / 64, 256>>>(x, n);
    k_scan1  <<<NBLK, 256>>>();
    k_scan2  <<<1, 512>>>(E);
    k_scan3  <<<256, 256>>>();
    k_scatter<<<2048, 256>>>(ei, E);
    k_fused  <<<(n * 32 + 255) / 256, 256>>>(out, att, bias, n);
}

// round 10
// speedup vs baseline: 1.5067x; 1.2565x over previous
#include <cuda_runtime.h>
#include <cuda_bf16.h>

#define NN 100000
#define DD 128
#define EE 1600000
#define NBLK 391   // ceil(NN/256)

// ---- scratch (__device__ globals per allocation-free rule) ----
__device__ float g_xl[(size_t)NN * DD];   // x @ W_l (hot: gathered 16x)
__device__ float g_xr[(size_t)NN * DD];   // x @ W_r (streamed once)
__device__ int   g_srcs[EE];
__device__ int   g_cnt[NN];
__device__ int   g_off[NN + 1];
__device__ int   g_cur[NN];
__device__ int   g_bsum[512];
__device__ int   g_is64;
// W pre-packed into bf16 mma-fragment layout: [ks(8)][j(32)][lane(32)][2] u32
__device__ unsigned g_wbh[16384];   // 64 KB hi component
__device__ unsigned g_wbl[16384];   // 64 KB lo component

__device__ __forceinline__ unsigned pkbf(float a, float b, float* ra, float* rb) {
    __nv_bfloat16 ha = __float2bfloat16(a), hb = __float2bfloat16(b);
    *ra = a - __bfloat162float(ha);
    *rb = b - __bfloat162float(hb);
    return (unsigned)__bfloat16_as_ushort(ha) |
           ((unsigned)__bfloat16_as_ushort(hb) << 16);
}
__device__ __forceinline__ unsigned pkbf2(float a, float b) {
    return (unsigned)__bfloat16_as_ushort(__float2bfloat16(a)) |
           ((unsigned)__bfloat16_as_ushort(__float2bfloat16(b)) << 16);
}
__device__ __forceinline__ void mma_bf16(float* c, const unsigned* a,
                                         unsigned b0, unsigned b1) {
    asm volatile(
        "mma.sync.aligned.m16n8k16.row.col.f32.bf16.bf16.f32 "
        "{%0,%1,%2,%3}, {%4,%5,%6,%7}, {%8,%9}, {%0,%1,%2,%3};"
        : "+f"(c[0]), "+f"(c[1]), "+f"(c[2]), "+f"(c[3])
        : "r"(a[0]), "r"(a[1]), "r"(a[2]), "r"(a[3]), "r"(b0), "r"(b1));
}

// ---------------------------------------------------------------------------
// K0: zero degree counters + detect edge dtype (int64 vs int32).
// ---------------------------------------------------------------------------
__global__ void k_zero(const int* __restrict__ ei_raw) {
    if (blockIdx.x == 0 && threadIdx.x == 0) {
        int all_zero = 1;
        for (int k = 0; k < 128; k++)
            if (ei_raw[2 * k + 1] != 0) { all_zero = 0; break; }
        g_is64 = all_zero;
    }
    for (int i = blockIdx.x * blockDim.x + threadIdx.x; i < NN;
         i += gridDim.x * blockDim.x)
        g_cnt[i] = 0;
}

__global__ void k_hist(const void* __restrict__ ei_raw, int E) {
    int is64 = g_is64;
    const long long* e64 = (const long long*)ei_raw;
    const int*       e32 = (const int*)ei_raw;
    for (int e = blockIdx.x * blockDim.x + threadIdx.x; e < E;
         e += gridDim.x * blockDim.x) {
        int d = is64 ? (int)__ldcs(&e64[E + e]) : __ldcs(&e32[E + e]);
        d = min(max(d, 0), NN - 1);
        atomicAdd(&g_cnt[d], 1);
    }
}

// ---------------------------------------------------------------------------
// pre-split + pre-pack W into per-lane bf16 fragment layout.
// For mma m16n8k16 row.col: lane l (g=l>>2, t=l&3) holds
//   b0 = {B[k0+2t][n], B[k0+2t+1][n]},  b1 = {B[k0+2t+8][n], B[k0+2t+9][n]}
// with n = j*8 + g, k0 = ks*16. n in 0..255 = [Wl | Wr] columns.
// ---------------------------------------------------------------------------
__global__ void k_prepw(const float* __restrict__ Wl,
                        const float* __restrict__ Wr) {
    int i = blockIdx.x * 256 + threadIdx.x;  // 8192 = 8ks * 32j * 32lane
    int lane = i & 31, j = (i >> 5) & 31, ks = i >> 10;
    int g = lane >> 2, t = lane & 3;
    int nc = j * 8 + g;
    const float* W = (nc < 128) ? Wl : Wr;
    int n = nc & 127;
    int k0 = ks * 16 + 2 * t;
    float w00 = W[(size_t)k0 * 128 + n];
    float w01 = W[(size_t)(k0 + 1) * 128 + n];
    float w10 = W[(size_t)(k0 + 8) * 128 + n];
    float w11 = W[(size_t)(k0 + 9) * 128 + n];
    float r0, r1, r2, r3;
    unsigned h0 = pkbf(w00, w01, &r0, &r1);
    unsigned h1 = pkbf(w10, w11, &r2, &r3);
    g_wbh[2 * i]     = h0;
    g_wbh[2 * i + 1] = h1;
    g_wbl[2 * i]     = pkbf2(r0, r1);
    g_wbl[2 * i + 1] = pkbf2(r2, r3);
}

// ---------------------------------------------------------------------------
// tensor dual GEMM via mma.sync bf16 m16n8k16, 3-way split (hi*hi+lo*hi+hi*lo).
// block 256 thr / 8 warps; tile M=64 x N=256; warp M32 x N64.
// Whole A tile staged once in smem (bf16 hi/lo, stride-68 conflict-free);
// B fragments read directly from pre-packed global (L2-resident, coalesced).
// ---------------------------------------------------------------------------
#define SA_STR 68   // u32 stride: banks (4g+t) all distinct -> conflict-free

__global__ __launch_bounds__(256, 2)
void k_tc(const float* __restrict__ x, int n) {
    __shared__ unsigned sAh[64 * SA_STR];
    __shared__ unsigned sAl[64 * SA_STR];

    int tid  = threadIdx.x;
    int lane = tid & 31;
    int wid  = tid >> 5;
    int row0  = blockIdx.x * 64;
    int mrow0 = (wid & 1) * 32;        // warp row offset
    int jbase = (wid >> 1) * 8;        // warp n-chunk base (0,8,16,24)

    // ---- stage whole A tile: 64 rows x 128 k -> bf16 hi/lo kpairs ----
    {
        int row = tid >> 2;            // 0..63
        int t4  = tid & 3;             // kpair range [16*t4, 16*t4+16)
        const float4* xr = (const float4*)(x + (size_t)(row0 + row) * 128 + t4 * 32);
        bool ok = (row0 + row) < n;
#pragma unroll
        for (int q = 0; q < 8; q++) {
            float4 f = ok ? __ldcs(&xr[q]) : make_float4(0.f, 0.f, 0.f, 0.f);
            float r0, r1, r2, r3;
            unsigned h0 = pkbf(f.x, f.y, &r0, &r1);
            unsigned h1 = pkbf(f.z, f.w, &r2, &r3);
            int kp = t4 * 16 + q * 2;
            sAh[row * SA_STR + kp]     = h0;
            sAh[row * SA_STR + kp + 1] = h1;
            sAl[row * SA_STR + kp]     = pkbf2(r0, r1);
            sAl[row * SA_STR + kp + 1] = pkbf2(r2, r3);
        }
    }
    __syncthreads();

    float acc[2][8][4] = {};
    int g = lane >> 2, t = lane & 3;

#pragma unroll
    for (int ks = 0; ks < 8; ks++) {
        // A fragments (hi & lo) for both m-chunks
        unsigned ah[2][4], al[2][4];
#pragma unroll
        for (int m = 0; m < 2; m++) {
            int r = mrow0 + m * 16 + g;
            int kp = ks * 8 + t;
            ah[m][0] = sAh[r * SA_STR + kp];
            ah[m][1] = sAh[(r + 8) * SA_STR + kp];
            ah[m][2] = sAh[r * SA_STR + kp + 4];
            ah[m][3] = sAh[(r + 8) * SA_STR + kp + 4];
            al[m][0] = sAl[r * SA_STR + kp];
            al[m][1] = sAl[(r + 8) * SA_STR + kp];
            al[m][2] = sAl[r * SA_STR + kp + 4];
            al[m][3] = sAl[(r + 8) * SA_STR + kp + 4];
        }
#pragma unroll
        for (int jj = 0; jj < 8; jj++) {
            int fidx = (ks * 32 + jbase + jj) * 32 + lane;
            uint2 bh = ((const uint2*)g_wbh)[fidx];
            uint2 bl = ((const uint2*)g_wbl)[fidx];
#pragma unroll
            for (int m = 0; m < 2; m++) {
                mma_bf16(acc[m][jj], ah[m], bh.x, bh.y);
                mma_bf16(acc[m][jj], al[m], bh.x, bh.y);
                mma_bf16(acc[m][jj], ah[m], bl.x, bl.y);
            }
        }
    }

    // epilogue: c0=(r,2t) c1=(r,2t+1) c2,c3=(r+8,...)
#pragma unroll
    for (int m = 0; m < 2; m++) {
        int row  = row0 + mrow0 + m * 16 + g;
        int row8 = row + 8;
#pragma unroll
        for (int jj = 0; jj < 8; jj++) {
            int col = (jbase + jj) * 8 + 2 * t;
            float* mat = (col < 128) ? g_xl : g_xr;
            int cc = col & 127;
            if (row < n)
                *(float2*)(mat + (size_t)row * 128 + cc) =
                    make_float2(acc[m][jj][0], acc[m][jj][1]);
            if (row8 < n)
                *(float2*)(mat + (size_t)row8 * 128 + cc) =
                    make_float2(acc[m][jj][2], acc[m][jj][3]);
        }
    }
}

// ---- 2-level exclusive scan of g_cnt -> g_off ----
__global__ void k_scan1() {
    __shared__ int s[256];
    int t = threadIdx.x;
    int i = blockIdx.x * 256 + t;
    int v = (i < NN) ? g_cnt[i] : 0;
    s[t] = v;
    __syncthreads();
#pragma unroll
    for (int d = 1; d < 256; d <<= 1) {
        int add = (t >= d) ? s[t - d] : 0;
        __syncthreads();
        s[t] += add;
        __syncthreads();
    }
    if (i < NN) g_off[i] = s[t] - v;
    if (t == 255) g_bsum[blockIdx.x] = s[255];
}

__global__ void k_scan2(int E) {
    __shared__ int s[512];
    int t = threadIdx.x;
    int v = (t < NBLK) ? g_bsum[t] : 0;
    s[t] = v;
    __syncthreads();
#pragma unroll
    for (int d = 1; d < 512; d <<= 1) {
        int add = (t >= d) ? s[t - d] : 0;
        __syncthreads();
        s[t] += add;
        __syncthreads();
    }
    if (t < NBLK) g_bsum[t] = s[t] - v;
    if (t == 0) g_off[NN] = E;
}

__global__ void k_scan3() {
    for (int i = blockIdx.x * blockDim.x + threadIdx.x; i < NN;
         i += gridDim.x * blockDim.x) {
        int o = g_off[i] + g_bsum[i >> 8];
        g_off[i] = o;
        g_cur[i] = o;
    }
}

__global__ void k_scatter(const void* __restrict__ ei_raw, int E) {
    int is64 = g_is64;
    const long long* e64 = (const long long*)ei_raw;
    const int*       e32 = (const int*)ei_raw;
    for (int e = blockIdx.x * blockDim.x + threadIdx.x; e < E;
         e += gridDim.x * blockDim.x) {
        int s, d;
        if (is64) { s = (int)__ldcs(&e64[e]); d = (int)__ldcs(&e64[E + e]); }
        else      { s = __ldcs(&e32[e]);      d = __ldcs(&e32[E + e]); }
        s = min(max(s, 0), NN - 1);
        d = min(max(d, 0), NN - 1);
        int pos = atomicAdd(&g_cur[d], 1);
        __stcs(&g_srcs[pos], s);
    }
}

// ---------------------------------------------------------------------------
// fused score + softmax + aggregate (proven): one warp per node, single pass.
// ---------------------------------------------------------------------------
__global__ void k_fused(float* __restrict__ out,
                        const float* __restrict__ att,
                        const float* __restrict__ bias, int n) {
    int node = (blockIdx.x * blockDim.x + threadIdx.x) >> 5;
    int lane = threadIdx.x & 31;
    if (node >= n) return;

    float4 a4 = ((const float4*)att)[lane];
    float c1x = 0.6f * a4.x, c1y = 0.6f * a4.y, c1z = 0.6f * a4.z, c1w = 0.6f * a4.w;
    float c2x = 0.4f * a4.x, c2y = 0.4f * a4.y, c2z = 0.4f * a4.z, c2w = 0.4f * a4.w;

    float4 xi = __ldcs(&((const float4*)(g_xr + (size_t)node * 128))[lane]);
    int beg = g_off[node];
    int end = g_off[node + 1];
    int lead = lane & 24;

    float4 acc = make_float4(0.f, 0.f, 0.f, 0.f);
    float den = 0.f;

    int p = beg;
    for (; p + 3 < end; p += 4) {
        int   si[4];
        float4 xj[4];
#pragma unroll
        for (int u = 0; u < 4; u++) si[u] = __ldcs(&g_srcs[p + u]);
#pragma unroll
        for (int u = 0; u < 4; u++)
            xj[u] = __ldg(&((const float4*)(g_xl + (size_t)si[u] * 128))[lane]);

        float sc[4];
#pragma unroll
        for (int u = 0; u < 4; u++) {
            float v, s;
            v = xi.x + xj[u].x; s  = c1x * v; s = fmaf(c2x, fabsf(v), s);
            v = xi.y + xj[u].y; s = fmaf(c1y, v, s); s = fmaf(c2y, fabsf(v), s);
            v = xi.z + xj[u].z; s = fmaf(c1z, v, s); s = fmaf(c2z, fabsf(v), s);
            v = xi.w + xj[u].w; s = fmaf(c1w, v, s); s = fmaf(c2w, fabsf(v), s);
            sc[u] = s;
        }
#pragma unroll
        for (int u = 0; u < 4; u++) sc[u] += __shfl_down_sync(0xffffffffu, sc[u], 4, 8);
#pragma unroll
        for (int u = 0; u < 4; u++) sc[u] += __shfl_down_sync(0xffffffffu, sc[u], 2, 8);
#pragma unroll
        for (int u = 0; u < 4; u++) sc[u] += __shfl_down_sync(0xffffffffu, sc[u], 1, 8);

        float ex[4];
        if ((lane & 7) == 0) {
#pragma unroll
            for (int u = 0; u < 4; u++) ex[u] = __expf(sc[u]);
        }
#pragma unroll
        for (int u = 0; u < 4; u++) ex[u] = __shfl_sync(0xffffffffu, ex[u], lead);

#pragma unroll
        for (int u = 0; u < 4; u++) {
            den += ex[u];
            acc.x = fmaf(ex[u], xj[u].x, acc.x);
            acc.y = fmaf(ex[u], xj[u].y, acc.y);
            acc.z = fmaf(ex[u], xj[u].z, acc.z);
            acc.w = fmaf(ex[u], xj[u].w, acc.w);
        }
    }
    for (; p < end; p++) {
        int s0 = __ldcs(&g_srcs[p]);
        float4 xj0 = __ldg(&((const float4*)(g_xl + (size_t)s0 * 128))[lane]);
        float v, s;
        v = xi.x + xj0.x; s  = c1x * v; s = fmaf(c2x, fabsf(v), s);
        v = xi.y + xj0.y; s = fmaf(c1y, v, s); s = fmaf(c2y, fabsf(v), s);
        v = xi.z + xj0.z; s = fmaf(c1z, v, s); s = fmaf(c2z, fabsf(v), s);
        v = xi.w + xj0.w; s = fmaf(c1w, v, s); s = fmaf(c2w, fabsf(v), s);
        s += __shfl_down_sync(0xffffffffu, s, 4, 8);
        s += __shfl_down_sync(0xffffffffu, s, 2, 8);
        s += __shfl_down_sync(0xffffffffu, s, 1, 8);
        float ex0;
        if ((lane & 7) == 0) ex0 = __expf(s);
        ex0 = __shfl_sync(0xffffffffu, ex0, lead);
        den += ex0;
        acc.x = fmaf(ex0, xj0.x, acc.x);
        acc.y = fmaf(ex0, xj0.y, acc.y);
        acc.z = fmaf(ex0, xj0.z, acc.z);
        acc.w = fmaf(ex0, xj0.w, acc.w);
    }

    float invd = 1.f / (den + 1e-16f);
    float4 b4 = ((const float4*)bias)[lane];
    float4 o;
    o.x = fmaf(acc.x, invd, b4.x);
    o.y = fmaf(acc.y, invd, b4.y);
    o.z = fmaf(acc.z, invd, b4.z);
    o.w = fmaf(acc.w, invd, b4.w);
    __stcs(&((float4*)(out + (size_t)node * 128))[lane], o);
}

extern "C" void kernel_launch(void* const* d_in, const int* in_sizes, int n_in,
                              void* d_out, int out_size) {
    const float* x    = (const float*)d_in[0];
    const void*  ei   = d_in[1];
    const float* Wl   = (const float*)d_in[2];
    const float* Wr   = (const float*)d_in[3];
    const float* att  = (const float*)d_in[4];
    const float* bias = (const float*)d_in[5];
    float*       out  = (float*)d_out;

    int n = in_sizes[0] / DD;   // 100000
    int E = in_sizes[1] / 2;    // 1600000

    // k_tc at launch index 3 (ncu samples launch #3)
    k_zero   <<<256, 256>>>((const int*)ei);
    k_hist   <<<2048, 256>>>(ei, E);
    k_prepw  <<<32, 256>>>(Wl, Wr);
    k_tc     <<<(n + 63) / 64, 256>>>(x, n);
    k_scan1  <<<NBLK, 256>>>();
    k_scan2  <<<1, 512>>>(E);
    k_scan3  <<<256, 256>>>();
    k_scatter<<<2048, 256>>>(ei, E);
    k_fused  <<<(n * 32 + 255) / 256, 256>>>(out, att, bias, n);
}

// round 11
// speedup vs baseline: 1.5629x; 1.0373x over previous
#include <cuda_runtime.h>
#include <cuda_bf16.h>

#define NN 100000
#define DD 128
#define EE 1600000
#define NBLK 391   // ceil(NN/256)

// ---- scratch (__device__ globals per allocation-free rule) ----
__device__ float g_xl[(size_t)NN * DD];   // x @ W_l (hot: gathered 16x)
__device__ float g_xr[(size_t)NN * DD];   // x @ W_r (streamed once)
__device__ int   g_srcs[EE];
__device__ int   g_cnt[NN];
__device__ int   g_off[NN + 1];
__device__ int   g_cur[NN];
__device__ int   g_bsum[512];
__device__ int   g_is64;
// W pre-packed into bf16 mma-fragment layout: [ks(8)][j(32)][lane(32)][2] u32
__device__ unsigned g_wbh[16384];   // 64 KB hi component
__device__ unsigned g_wbl[16384];   // 64 KB lo component

__device__ __forceinline__ unsigned pkbf(float a, float b, float* ra, float* rb) {
    __nv_bfloat16 ha = __float2bfloat16(a), hb = __float2bfloat16(b);
    *ra = a - __bfloat162float(ha);
    *rb = b - __bfloat162float(hb);
    return (unsigned)__bfloat16_as_ushort(ha) |
           ((unsigned)__bfloat16_as_ushort(hb) << 16);
}
__device__ __forceinline__ unsigned pkbf2(float a, float b) {
    return (unsigned)__bfloat16_as_ushort(__float2bfloat16(a)) |
           ((unsigned)__bfloat16_as_ushort(__float2bfloat16(b)) << 16);
}
__device__ __forceinline__ void mma_bf16(float* c, const unsigned* a,
                                         unsigned b0, unsigned b1) {
    asm volatile(
        "mma.sync.aligned.m16n8k16.row.col.f32.bf16.bf16.f32 "
        "{%0,%1,%2,%3}, {%4,%5,%6,%7}, {%8,%9}, {%0,%1,%2,%3};"
        : "+f"(c[0]), "+f"(c[1]), "+f"(c[2]), "+f"(c[3])
        : "r"(a[0]), "r"(a[1]), "r"(a[2]), "r"(a[3]), "r"(b0), "r"(b1));
}

// ---------------------------------------------------------------------------
// K0: zero degree counters + detect edge dtype (int64 vs int32).
// ---------------------------------------------------------------------------
__global__ void k_zero(const int* __restrict__ ei_raw) {
    if (blockIdx.x == 0 && threadIdx.x == 0) {
        int all_zero = 1;
        for (int k = 0; k < 128; k++)
            if (ei_raw[2 * k + 1] != 0) { all_zero = 0; break; }
        g_is64 = all_zero;
    }
    for (int i = blockIdx.x * blockDim.x + threadIdx.x; i < NN;
         i += gridDim.x * blockDim.x)
        g_cnt[i] = 0;
}

__global__ void k_hist(const void* __restrict__ ei_raw, int E) {
    int is64 = g_is64;
    const long long* e64 = (const long long*)ei_raw;
    const int*       e32 = (const int*)ei_raw;
    for (int e = blockIdx.x * blockDim.x + threadIdx.x; e < E;
         e += gridDim.x * blockDim.x) {
        int d = is64 ? (int)__ldcs(&e64[E + e]) : __ldcs(&e32[E + e]);
        d = min(max(d, 0), NN - 1);
        atomicAdd(&g_cnt[d], 1);
    }
}

// ---------------------------------------------------------------------------
// pre-split + pre-pack W into per-lane bf16 fragment layout.
// ---------------------------------------------------------------------------
__global__ void k_prepw(const float* __restrict__ Wl,
                        const float* __restrict__ Wr) {
    int i = blockIdx.x * 256 + threadIdx.x;  // 8192 = 8ks * 32j * 32lane
    int lane = i & 31, j = (i >> 5) & 31, ks = i >> 10;
    int g = lane >> 2, t = lane & 3;
    int nc = j * 8 + g;
    const float* W = (nc < 128) ? Wl : Wr;
    int n = nc & 127;
    int k0 = ks * 16 + 2 * t;
    float w00 = W[(size_t)k0 * 128 + n];
    float w01 = W[(size_t)(k0 + 1) * 128 + n];
    float w10 = W[(size_t)(k0 + 8) * 128 + n];
    float w11 = W[(size_t)(k0 + 9) * 128 + n];
    float r0, r1, r2, r3;
    unsigned h0 = pkbf(w00, w01, &r0, &r1);
    unsigned h1 = pkbf(w10, w11, &r2, &r3);
    g_wbh[2 * i]     = h0;
    g_wbh[2 * i + 1] = h1;
    g_wbl[2 * i]     = pkbf2(r0, r1);
    g_wbl[2 * i + 1] = pkbf2(r2, r3);
}

// ---------------------------------------------------------------------------
// tensor dual GEMM via mma.sync bf16 m16n8k16, 3-way split (hi*hi+lo*hi+hi*lo).
// ---------------------------------------------------------------------------
#define SA_STR 68   // u32 stride: banks (4g+t) all distinct -> conflict-free

__global__ __launch_bounds__(256, 2)
void k_tc(const float* __restrict__ x, int n) {
    __shared__ unsigned sAh[64 * SA_STR];
    __shared__ unsigned sAl[64 * SA_STR];

    int tid  = threadIdx.x;
    int lane = tid & 31;
    int wid  = tid >> 5;
    int row0  = blockIdx.x * 64;
    int mrow0 = (wid & 1) * 32;        // warp row offset
    int jbase = (wid >> 1) * 8;        // warp n-chunk base (0,8,16,24)

    // ---- stage whole A tile: 64 rows x 128 k -> bf16 hi/lo kpairs ----
    {
        int row = tid >> 2;            // 0..63
        int t4  = tid & 3;             // kpair range [16*t4, 16*t4+16)
        const float4* xr = (const float4*)(x + (size_t)(row0 + row) * 128 + t4 * 32);
        bool ok = (row0 + row) < n;
#pragma unroll
        for (int q = 0; q < 8; q++) {
            float4 f = ok ? __ldcs(&xr[q]) : make_float4(0.f, 0.f, 0.f, 0.f);
            float r0, r1, r2, r3;
            unsigned h0 = pkbf(f.x, f.y, &r0, &r1);
            unsigned h1 = pkbf(f.z, f.w, &r2, &r3);
            int kp = t4 * 16 + q * 2;
            sAh[row * SA_STR + kp]     = h0;
            sAh[row * SA_STR + kp + 1] = h1;
            sAl[row * SA_STR + kp]     = pkbf2(r0, r1);
            sAl[row * SA_STR + kp + 1] = pkbf2(r2, r3);
        }
    }
    __syncthreads();

    float acc[2][8][4] = {};
    int g = lane >> 2, t = lane & 3;

#pragma unroll
    for (int ks = 0; ks < 8; ks++) {
        unsigned ah[2][4], al[2][4];
#pragma unroll
        for (int m = 0; m < 2; m++) {
            int r = mrow0 + m * 16 + g;
            int kp = ks * 8 + t;
            ah[m][0] = sAh[r * SA_STR + kp];
            ah[m][1] = sAh[(r + 8) * SA_STR + kp];
            ah[m][2] = sAh[r * SA_STR + kp + 4];
            ah[m][3] = sAh[(r + 8) * SA_STR + kp + 4];
            al[m][0] = sAl[r * SA_STR + kp];
            al[m][1] = sAl[(r + 8) * SA_STR + kp];
            al[m][2] = sAl[r * SA_STR + kp + 4];
            al[m][3] = sAl[(r + 8) * SA_STR + kp + 4];
        }
#pragma unroll
        for (int jj = 0; jj < 8; jj++) {
            int fidx = (ks * 32 + jbase + jj) * 32 + lane;
            uint2 bh = ((const uint2*)g_wbh)[fidx];
            uint2 bl = ((const uint2*)g_wbl)[fidx];
#pragma unroll
            for (int m = 0; m < 2; m++) {
                mma_bf16(acc[m][jj], ah[m], bh.x, bh.y);
                mma_bf16(acc[m][jj], al[m], bh.x, bh.y);
                mma_bf16(acc[m][jj], ah[m], bl.x, bl.y);
            }
        }
    }

#pragma unroll
    for (int m = 0; m < 2; m++) {
        int row  = row0 + mrow0 + m * 16 + g;
        int row8 = row + 8;
#pragma unroll
        for (int jj = 0; jj < 8; jj++) {
            int col = (jbase + jj) * 8 + 2 * t;
            float* mat = (col < 128) ? g_xl : g_xr;
            int cc = col & 127;
            if (row < n)
                *(float2*)(mat + (size_t)row * 128 + cc) =
                    make_float2(acc[m][jj][0], acc[m][jj][1]);
            if (row8 < n)
                *(float2*)(mat + (size_t)row8 * 128 + cc) =
                    make_float2(acc[m][jj][2], acc[m][jj][3]);
        }
    }
}

// ---- 2-level exclusive scan of g_cnt -> g_off ----
__global__ void k_scan1() {
    __shared__ int s[256];
    int t = threadIdx.x;
    int i = blockIdx.x * 256 + t;
    int v = (i < NN) ? g_cnt[i] : 0;
    s[t] = v;
    __syncthreads();
#pragma unroll
    for (int d = 1; d < 256; d <<= 1) {
        int add = (t >= d) ? s[t - d] : 0;
        __syncthreads();
        s[t] += add;
        __syncthreads();
    }
    if (i < NN) g_off[i] = s[t] - v;
    if (t == 255) g_bsum[blockIdx.x] = s[255];
}

__global__ void k_scan2(int E) {
    __shared__ int s[512];
    int t = threadIdx.x;
    int v = (t < NBLK) ? g_bsum[t] : 0;
    s[t] = v;
    __syncthreads();
#pragma unroll
    for (int d = 1; d < 512; d <<= 1) {
        int add = (t >= d) ? s[t - d] : 0;
        __syncthreads();
        s[t] += add;
        __syncthreads();
    }
    if (t < NBLK) g_bsum[t] = s[t] - v;
    if (t == 0) g_off[NN] = E;
}

__global__ void k_scan3() {
    for (int i = blockIdx.x * blockDim.x + threadIdx.x; i < NN;
         i += gridDim.x * blockDim.x) {
        int o = g_off[i] + g_bsum[i >> 8];
        g_off[i] = o;
        g_cur[i] = o;
    }
}

__global__ void k_scatter(const void* __restrict__ ei_raw, int E) {
    int is64 = g_is64;
    const long long* e64 = (const long long*)ei_raw;
    const int*       e32 = (const int*)ei_raw;
    for (int e = blockIdx.x * blockDim.x + threadIdx.x; e < E;
         e += gridDim.x * blockDim.x) {
        int s, d;
        if (is64) { s = (int)__ldcs(&e64[e]); d = (int)__ldcs(&e64[E + e]); }
        else      { s = __ldcs(&e32[e]);      d = __ldcs(&e32[E + e]); }
        s = min(max(s, 0), NN - 1);
        d = min(max(d, 0), NN - 1);
        int pos = atomicAdd(&g_cur[d], 1);
        __stcs(&g_srcs[pos], s);
    }
}

// ---------------------------------------------------------------------------
// fused score + softmax + aggregate (proven): one warp per node, single pass.
// ---------------------------------------------------------------------------
__global__ void k_fused(float* __restrict__ out,
                        const float* __restrict__ att,
                        const float* __restrict__ bias, int n) {
    int node = (blockIdx.x * blockDim.x + threadIdx.x) >> 5;
    int lane = threadIdx.x & 31;
    if (node >= n) return;

    float4 a4 = ((const float4*)att)[lane];
    float c1x = 0.6f * a4.x, c1y = 0.6f * a4.y, c1z = 0.6f * a4.z, c1w = 0.6f * a4.w;
    float c2x = 0.4f * a4.x, c2y = 0.4f * a4.y, c2z = 0.4f * a4.z, c2w = 0.4f * a4.w;

    float4 xi = __ldcs(&((const float4*)(g_xr + (size_t)node * 128))[lane]);
    int beg = g_off[node];
    int end = g_off[node + 1];
    int lead = lane & 24;

    float4 acc = make_float4(0.f, 0.f, 0.f, 0.f);
    float den = 0.f;

    int p = beg;
    for (; p + 3 < end; p += 4) {
        int   si[4];
        float4 xj[4];
#pragma unroll
        for (int u = 0; u < 4; u++) si[u] = __ldcs(&g_srcs[p + u]);
#pragma unroll
        for (int u = 0; u < 4; u++)
            xj[u] = __ldg(&((const float4*)(g_xl + (size_t)si[u] * 128))[lane]);

        float sc[4];
#pragma unroll
        for (int u = 0; u < 4; u++) {
            float v, s;
            v = xi.x + xj[u].x; s  = c1x * v; s = fmaf(c2x, fabsf(v), s);
            v = xi.y + xj[u].y; s = fmaf(c1y, v, s); s = fmaf(c2y, fabsf(v), s);
            v = xi.z + xj[u].z; s = fmaf(c1z, v, s); s = fmaf(c2z, fabsf(v), s);
            v = xi.w + xj[u].w; s = fmaf(c1w, v, s); s = fmaf(c2w, fabsf(v), s);
            sc[u] = s;
        }
#pragma unroll
        for (int u = 0; u < 4; u++) sc[u] += __shfl_down_sync(0xffffffffu, sc[u], 4, 8);
#pragma unroll
        for (int u = 0; u < 4; u++) sc[u] += __shfl_down_sync(0xffffffffu, sc[u], 2, 8);
#pragma unroll
        for (int u = 0; u < 4; u++) sc[u] += __shfl_down_sync(0xffffffffu, sc[u], 1, 8);

        float ex[4];
        if ((lane & 7) == 0) {
#pragma unroll
            for (int u = 0; u < 4; u++) ex[u] = __expf(sc[u]);
        }
#pragma unroll
        for (int u = 0; u < 4; u++) ex[u] = __shfl_sync(0xffffffffu, ex[u], lead);

#pragma unroll
        for (int u = 0; u < 4; u++) {
            den += ex[u];
            acc.x = fmaf(ex[u], xj[u].x, acc.x);
            acc.y = fmaf(ex[u], xj[u].y, acc.y);
            acc.z = fmaf(ex[u], xj[u].z, acc.z);
            acc.w = fmaf(ex[u], xj[u].w, acc.w);
        }
    }
    for (; p < end; p++) {
        int s0 = __ldcs(&g_srcs[p]);
        float4 xj0 = __ldg(&((const float4*)(g_xl + (size_t)s0 * 128))[lane]);
        float v, s;
        v = xi.x + xj0.x; s  = c1x * v; s = fmaf(c2x, fabsf(v), s);
        v = xi.y + xj0.y; s = fmaf(c1y, v, s); s = fmaf(c2y, fabsf(v), s);
        v = xi.z + xj0.z; s = fmaf(c1z, v, s); s = fmaf(c2z, fabsf(v), s);
        v = xi.w + xj0.w; s = fmaf(c1w, v, s); s = fmaf(c2w, fabsf(v), s);
        s += __shfl_down_sync(0xffffffffu, s, 4, 8);
        s += __shfl_down_sync(0xffffffffu, s, 2, 8);
        s += __shfl_down_sync(0xffffffffu, s, 1, 8);
        float ex0;
        if ((lane & 7) == 0) ex0 = __expf(s);
        ex0 = __shfl_sync(0xffffffffu, ex0, lead);
        den += ex0;
        acc.x = fmaf(ex0, xj0.x, acc.x);
        acc.y = fmaf(ex0, xj0.y, acc.y);
        acc.z = fmaf(ex0, xj0.z, acc.z);
        acc.w = fmaf(ex0, xj0.w, acc.w);
    }

    float invd = 1.f / (den + 1e-16f);
    float4 b4 = ((const float4*)bias)[lane];
    float4 o;
    o.x = fmaf(acc.x, invd, b4.x);
    o.y = fmaf(acc.y, invd, b4.y);
    o.z = fmaf(acc.z, invd, b4.z);
    o.w = fmaf(acc.w, invd, b4.w);
    __stcs(&((float4*)(out + (size_t)node * 128))[lane], o);
}

extern "C" void kernel_launch(void* const* d_in, const int* in_sizes, int n_in,
                              void* d_out, int out_size) {
    const float* x    = (const float*)d_in[0];
    const void*  ei   = d_in[1];
    const float* Wl   = (const float*)d_in[2];
    const float* Wr   = (const float*)d_in[3];
    const float* att  = (const float*)d_in[4];
    const float* bias = (const float*)d_in[5];
    float*       out  = (float*)d_out;

    int n = in_sizes[0] / DD;   // 100000
    int E = in_sizes[1] / 2;    // 1600000

    // Fork-join: GEMM branch (prepw -> k_tc) runs concurrently with the
    // edge-CSR branch (zero -> hist -> scans -> scatter); join before k_fused.
    // Non-blocking stream avoids legacy-default-stream implicit sync.
    // (Stream/events intentionally not destroyed: kernel_launch is invoked
    // only a handful of times; destruction during capture is illegal.)
    cudaStream_t s2;
    cudaEvent_t evFork, evJoin;
    cudaStreamCreateWithFlags(&s2, cudaStreamNonBlocking);
    cudaEventCreateWithFlags(&evFork, cudaEventDisableTiming);
    cudaEventCreateWithFlags(&evJoin, cudaEventDisableTiming);

    cudaEventRecord(evFork, 0);
    cudaStreamWaitEvent(s2, evFork, 0);
    k_prepw<<<32, 256, 0, s2>>>(Wl, Wr);
    k_tc   <<<(n + 63) / 64, 256, 0, s2>>>(x, n);
    cudaEventRecord(evJoin, s2);

    k_zero   <<<256, 256>>>((const int*)ei);
    k_hist   <<<2048, 256>>>(ei, E);
    k_scan1  <<<NBLK, 256>>>();
    k_scan2  <<<1, 512>>>(E);
    k_scan3  <<<256, 256>>>();
    k_scatter<<<2048, 256>>>(ei, E);

    cudaStreamWaitEvent(0, evJoin, 0);
    k_fused  <<<(n * 32 + 255) / 256, 256>>>(out, att, bias, n);
}

// round 12
// speedup vs baseline: 1.5944x; 1.0202x over previous
#include <cuda_runtime.h>
#include <cuda_bf16.h>
#include <cuda_fp16.h>

#define NN 100000
#define DD 128
#define EE 1600000
#define NBLK 391   // ceil(NN/256)

// ---- scratch (__device__ globals per allocation-free rule) ----
__device__ unsigned g_xlh[(size_t)NN * 64]; // xl as half2 pairs (25.6 MB, L2-resident)
__device__ float    g_xr[(size_t)NN * DD];  // x @ W_r (streamed once)
__device__ int      g_srcs[EE];
__device__ int      g_cnt[NN];
__device__ int      g_off[NN + 1];
__device__ int      g_cur[NN];
__device__ int      g_bsum[512];
__device__ int      g_is64;
// W pre-packed into bf16 mma-fragment layout: [ks(8)][j(32)][lane(32)][2] u32
__device__ unsigned g_wbh[16384];   // 64 KB hi component
__device__ unsigned g_wbl[16384];   // 64 KB lo component

__device__ __forceinline__ unsigned pkbf(float a, float b, float* ra, float* rb) {
    __nv_bfloat16 ha = __float2bfloat16(a), hb = __float2bfloat16(b);
    *ra = a - __bfloat162float(ha);
    *rb = b - __bfloat162float(hb);
    return (unsigned)__bfloat16_as_ushort(ha) |
           ((unsigned)__bfloat16_as_ushort(hb) << 16);
}
__device__ __forceinline__ unsigned pkbf2(float a, float b) {
    return (unsigned)__bfloat16_as_ushort(__float2bfloat16(a)) |
           ((unsigned)__bfloat16_as_ushort(__float2bfloat16(b)) << 16);
}
__device__ __forceinline__ void mma_bf16(float* c, const unsigned* a,
                                         unsigned b0, unsigned b1) {
    asm volatile(
        "mma.sync.aligned.m16n8k16.row.col.f32.bf16.bf16.f32 "
        "{%0,%1,%2,%3}, {%4,%5,%6,%7}, {%8,%9}, {%0,%1,%2,%3};"
        : "+f"(c[0]), "+f"(c[1]), "+f"(c[2]), "+f"(c[3])
        : "r"(a[0]), "r"(a[1]), "r"(a[2]), "r"(a[3]), "r"(b0), "r"(b1));
}

// ---------------------------------------------------------------------------
// K0: zero degree counters + detect edge dtype (int64 vs int32).
// ---------------------------------------------------------------------------
__global__ void k_zero(const int* __restrict__ ei_raw) {
    if (blockIdx.x == 0 && threadIdx.x == 0) {
        int all_zero = 1;
        for (int k = 0; k < 128; k++)
            if (ei_raw[2 * k + 1] != 0) { all_zero = 0; break; }
        g_is64 = all_zero;
    }
    for (int i = blockIdx.x * blockDim.x + threadIdx.x; i < NN;
         i += gridDim.x * blockDim.x)
        g_cnt[i] = 0;
}

__global__ void k_hist(const void* __restrict__ ei_raw, int E) {
    int is64 = g_is64;
    const long long* e64 = (const long long*)ei_raw;
    const int*       e32 = (const int*)ei_raw;
    for (int e = blockIdx.x * blockDim.x + threadIdx.x; e < E;
         e += gridDim.x * blockDim.x) {
        int d = is64 ? (int)__ldcs(&e64[E + e]) : __ldcs(&e32[E + e]);
        d = min(max(d, 0), NN - 1);
        atomicAdd(&g_cnt[d], 1);
    }
}

// ---------------------------------------------------------------------------
// pre-split + pre-pack W into per-lane bf16 fragment layout.
// ---------------------------------------------------------------------------
__global__ void k_prepw(const float* __restrict__ Wl,
                        const float* __restrict__ Wr) {
    int i = blockIdx.x * 256 + threadIdx.x;  // 8192 = 8ks * 32j * 32lane
    int lane = i & 31, j = (i >> 5) & 31, ks = i >> 10;
    int g = lane >> 2, t = lane & 3;
    int nc = j * 8 + g;
    const float* W = (nc < 128) ? Wl : Wr;
    int n = nc & 127;
    int k0 = ks * 16 + 2 * t;
    float w00 = W[(size_t)k0 * 128 + n];
    float w01 = W[(size_t)(k0 + 1) * 128 + n];
    float w10 = W[(size_t)(k0 + 8) * 128 + n];
    float w11 = W[(size_t)(k0 + 9) * 128 + n];
    float r0, r1, r2, r3;
    unsigned h0 = pkbf(w00, w01, &r0, &r1);
    unsigned h1 = pkbf(w10, w11, &r2, &r3);
    g_wbh[2 * i]     = h0;
    g_wbh[2 * i + 1] = h1;
    g_wbl[2 * i]     = pkbf2(r0, r1);
    g_wbl[2 * i + 1] = pkbf2(r2, r3);
}

// ---------------------------------------------------------------------------
// tensor dual GEMM via mma.sync bf16 m16n8k16, 3-way split (hi*hi+lo*hi+hi*lo).
// xl results stored as half2 (gathered tensor); xr as fp32.
// ---------------------------------------------------------------------------
#define SA_STR 68   // u32 stride: banks (4g+t) all distinct -> conflict-free

__global__ __launch_bounds__(256, 2)
void k_tc(const float* __restrict__ x, int n) {
    __shared__ unsigned sAh[64 * SA_STR];
    __shared__ unsigned sAl[64 * SA_STR];

    int tid  = threadIdx.x;
    int lane = tid & 31;
    int wid  = tid >> 5;
    int row0  = blockIdx.x * 64;
    int mrow0 = (wid & 1) * 32;        // warp row offset
    int jbase = (wid >> 1) * 8;        // warp n-chunk base (0,8,16,24)

    // ---- stage whole A tile: 64 rows x 128 k -> bf16 hi/lo kpairs ----
    {
        int row = tid >> 2;            // 0..63
        int t4  = tid & 3;             // kpair range [16*t4, 16*t4+16)
        const float4* xr = (const float4*)(x + (size_t)(row0 + row) * 128 + t4 * 32);
        bool ok = (row0 + row) < n;
#pragma unroll
        for (int q = 0; q < 8; q++) {
            float4 f = ok ? __ldcs(&xr[q]) : make_float4(0.f, 0.f, 0.f, 0.f);
            float r0, r1, r2, r3;
            unsigned h0 = pkbf(f.x, f.y, &r0, &r1);
            unsigned h1 = pkbf(f.z, f.w, &r2, &r3);
            int kp = t4 * 16 + q * 2;
            sAh[row * SA_STR + kp]     = h0;
            sAh[row * SA_STR + kp + 1] = h1;
            sAl[row * SA_STR + kp]     = pkbf2(r0, r1);
            sAl[row * SA_STR + kp + 1] = pkbf2(r2, r3);
        }
    }
    __syncthreads();

    float acc[2][8][4] = {};
    int g = lane >> 2, t = lane & 3;

#pragma unroll
    for (int ks = 0; ks < 8; ks++) {
        unsigned ah[2][4], al[2][4];
#pragma unroll
        for (int m = 0; m < 2; m++) {
            int r = mrow0 + m * 16 + g;
            int kp = ks * 8 + t;
            ah[m][0] = sAh[r * SA_STR + kp];
            ah[m][1] = sAh[(r + 8) * SA_STR + kp];
            ah[m][2] = sAh[r * SA_STR + kp + 4];
            ah[m][3] = sAh[(r + 8) * SA_STR + kp + 4];
            al[m][0] = sAl[r * SA_STR + kp];
            al[m][1] = sAl[(r + 8) * SA_STR + kp];
            al[m][2] = sAl[r * SA_STR + kp + 4];
            al[m][3] = sAl[(r + 8) * SA_STR + kp + 4];
        }
#pragma unroll
        for (int jj = 0; jj < 8; jj++) {
            int fidx = (ks * 32 + jbase + jj) * 32 + lane;
            uint2 bh = ((const uint2*)g_wbh)[fidx];
            uint2 bl = ((const uint2*)g_wbl)[fidx];
#pragma unroll
            for (int m = 0; m < 2; m++) {
                mma_bf16(acc[m][jj], ah[m], bh.x, bh.y);
                mma_bf16(acc[m][jj], al[m], bh.x, bh.y);
                mma_bf16(acc[m][jj], ah[m], bl.x, bl.y);
            }
        }
    }

#pragma unroll
    for (int m = 0; m < 2; m++) {
        int row  = row0 + mrow0 + m * 16 + g;
        int row8 = row + 8;
#pragma unroll
        for (int jj = 0; jj < 8; jj++) {
            int col = (jbase + jj) * 8 + 2 * t;
            if (col < 128) {
                // xl -> half2
                __half2 h01 = __floats2half2_rn(acc[m][jj][0], acc[m][jj][1]);
                __half2 h23 = __floats2half2_rn(acc[m][jj][2], acc[m][jj][3]);
                if (row < n)
                    g_xlh[(size_t)row * 64 + (col >> 1)] = *(unsigned*)&h01;
                if (row8 < n)
                    g_xlh[(size_t)row8 * 64 + (col >> 1)] = *(unsigned*)&h23;
            } else {
                int cc = col & 127;
                if (row < n)
                    *(float2*)(g_xr + (size_t)row * 128 + cc) =
                        make_float2(acc[m][jj][0], acc[m][jj][1]);
                if (row8 < n)
                    *(float2*)(g_xr + (size_t)row8 * 128 + cc) =
                        make_float2(acc[m][jj][2], acc[m][jj][3]);
            }
        }
    }
}

// ---- 2-level exclusive scan of g_cnt -> g_off ----
__global__ void k_scan1() {
    __shared__ int s[256];
    int t = threadIdx.x;
    int i = blockIdx.x * 256 + t;
    int v = (i < NN) ? g_cnt[i] : 0;
    s[t] = v;
    __syncthreads();
#pragma unroll
    for (int d = 1; d < 256; d <<= 1) {
        int add = (t >= d) ? s[t - d] : 0;
        __syncthreads();
        s[t] += add;
        __syncthreads();
    }
    if (i < NN) g_off[i] = s[t] - v;
    if (t == 255) g_bsum[blockIdx.x] = s[255];
}

__global__ void k_scan2(int E) {
    __shared__ int s[512];
    int t = threadIdx.x;
    int v = (t < NBLK) ? g_bsum[t] : 0;
    s[t] = v;
    __syncthreads();
#pragma unroll
    for (int d = 1; d < 512; d <<= 1) {
        int add = (t >= d) ? s[t - d] : 0;
        __syncthreads();
        s[t] += add;
        __syncthreads();
    }
    if (t < NBLK) g_bsum[t] = s[t] - v;
    if (t == 0) g_off[NN] = E;
}

__global__ void k_scan3() {
    for (int i = blockIdx.x * blockDim.x + threadIdx.x; i < NN;
         i += gridDim.x * blockDim.x) {
        int o = g_off[i] + g_bsum[i >> 8];
        g_off[i] = o;
        g_cur[i] = o;
    }
}

__global__ void k_scatter(const void* __restrict__ ei_raw, int E) {
    int is64 = g_is64;
    const long long* e64 = (const long long*)ei_raw;
    const int*       e32 = (const int*)ei_raw;
    for (int e = blockIdx.x * blockDim.x + threadIdx.x; e < E;
         e += gridDim.x * blockDim.x) {
        int s, d;
        if (is64) { s = (int)__ldcs(&e64[e]); d = (int)__ldcs(&e64[E + e]); }
        else      { s = __ldcs(&e32[e]);      d = __ldcs(&e32[E + e]); }
        s = min(max(s, 0), NN - 1);
        d = min(max(d, 0), NN - 1);
        int pos = atomicAdd(&g_cur[d], 1);
        __stcs(&g_srcs[pos], s);
    }
}

// ---------------------------------------------------------------------------
// fused score + softmax + aggregate: one warp per node, single pass.
// xl gathered as half2 (half traffic, fully L2-resident).
// ---------------------------------------------------------------------------
__global__ void k_fused(float* __restrict__ out,
                        const float* __restrict__ att,
                        const float* __restrict__ bias, int n) {
    int node = (blockIdx.x * blockDim.x + threadIdx.x) >> 5;
    int lane = threadIdx.x & 31;
    if (node >= n) return;

    float4 a4 = ((const float4*)att)[lane];
    float c1x = 0.6f * a4.x, c1y = 0.6f * a4.y, c1z = 0.6f * a4.z, c1w = 0.6f * a4.w;
    float c2x = 0.4f * a4.x, c2y = 0.4f * a4.y, c2z = 0.4f * a4.z, c2w = 0.4f * a4.w;

    float4 xi = __ldcs(&((const float4*)(g_xr + (size_t)node * 128))[lane]);
    int beg = g_off[node];
    int end = g_off[node + 1];
    int lead = lane & 24;

    float4 acc = make_float4(0.f, 0.f, 0.f, 0.f);
    float den = 0.f;

    int p = beg;
    for (; p + 3 < end; p += 4) {
        int  si[4];
        uint2 xu[4];
#pragma unroll
        for (int u = 0; u < 4; u++) si[u] = __ldcs(&g_srcs[p + u]);
#pragma unroll
        for (int u = 0; u < 4; u++)
            xu[u] = __ldg(&((const uint2*)g_xlh)[(size_t)si[u] * 32 + lane]);

        float4 xj[4];
        float sc[4];
#pragma unroll
        for (int u = 0; u < 4; u++) {
            float2 f01 = __half22float2(*(__half2*)&xu[u].x);
            float2 f23 = __half22float2(*(__half2*)&xu[u].y);
            xj[u] = make_float4(f01.x, f01.y, f23.x, f23.y);
            float v, s;
            v = xi.x + xj[u].x; s  = c1x * v; s = fmaf(c2x, fabsf(v), s);
            v = xi.y + xj[u].y; s = fmaf(c1y, v, s); s = fmaf(c2y, fabsf(v), s);
            v = xi.z + xj[u].z; s = fmaf(c1z, v, s); s = fmaf(c2z, fabsf(v), s);
            v = xi.w + xj[u].w; s = fmaf(c1w, v, s); s = fmaf(c2w, fabsf(v), s);
            sc[u] = s;
        }
#pragma unroll
        for (int u = 0; u < 4; u++) sc[u] += __shfl_down_sync(0xffffffffu, sc[u], 4, 8);
#pragma unroll
        for (int u = 0; u < 4; u++) sc[u] += __shfl_down_sync(0xffffffffu, sc[u], 2, 8);
#pragma unroll
        for (int u = 0; u < 4; u++) sc[u] += __shfl_down_sync(0xffffffffu, sc[u], 1, 8);

        float ex[4];
        if ((lane & 7) == 0) {
#pragma unroll
            for (int u = 0; u < 4; u++) ex[u] = __expf(sc[u]);
        }
#pragma unroll
        for (int u = 0; u < 4; u++) ex[u] = __shfl_sync(0xffffffffu, ex[u], lead);

#pragma unroll
        for (int u = 0; u < 4; u++) {
            den += ex[u];
            acc.x = fmaf(ex[u], xj[u].x, acc.x);
            acc.y = fmaf(ex[u], xj[u].y, acc.y);
            acc.z = fmaf(ex[u], xj[u].z, acc.z);
            acc.w = fmaf(ex[u], xj[u].w, acc.w);
        }
    }
    for (; p < end; p++) {
        int s0 = __ldcs(&g_srcs[p]);
        uint2 xu = __ldg(&((const uint2*)g_xlh)[(size_t)s0 * 32 + lane]);
        float2 f01 = __half22float2(*(__half2*)&xu.x);
        float2 f23 = __half22float2(*(__half2*)&xu.y);
        float4 xj0 = make_float4(f01.x, f01.y, f23.x, f23.y);
        float v, s;
        v = xi.x + xj0.x; s  = c1x * v; s = fmaf(c2x, fabsf(v), s);
        v = xi.y + xj0.y; s = fmaf(c1y, v, s); s = fmaf(c2y, fabsf(v), s);
        v = xi.z + xj0.z; s = fmaf(c1z, v, s); s = fmaf(c2z, fabsf(v), s);
        v = xi.w + xj0.w; s = fmaf(c1w, v, s); s = fmaf(c2w, fabsf(v), s);
        s += __shfl_down_sync(0xffffffffu, s, 4, 8);
        s += __shfl_down_sync(0xffffffffu, s, 2, 8);
        s += __shfl_down_sync(0xffffffffu, s, 1, 8);
        float ex0;
        if ((lane & 7) == 0) ex0 = __expf(s);
        ex0 = __shfl_sync(0xffffffffu, ex0, lead);
        den += ex0;
        acc.x = fmaf(ex0, xj0.x, acc.x);
        acc.y = fmaf(ex0, xj0.y, acc.y);
        acc.z = fmaf(ex0, xj0.z, acc.z);
        acc.w = fmaf(ex0, xj0.w, acc.w);
    }

    float invd = 1.f / (den + 1e-16f);
    float4 b4 = ((const float4*)bias)[lane];
    float4 o;
    o.x = fmaf(acc.x, invd, b4.x);
    o.y = fmaf(acc.y, invd, b4.y);
    o.z = fmaf(acc.z, invd, b4.z);
    o.w = fmaf(acc.w, invd, b4.w);
    __stcs(&((float4*)(out + (size_t)node * 128))[lane], o);
}

extern "C" void kernel_launch(void* const* d_in, const int* in_sizes, int n_in,
                              void* d_out, int out_size) {
    const float* x    = (const float*)d_in[0];
    const void*  ei   = d_in[1];
    const float* Wl   = (const float*)d_in[2];
    const float* Wr   = (const float*)d_in[3];
    const float* att  = (const float*)d_in[4];
    const float* bias = (const float*)d_in[5];
    float*       out  = (float*)d_out;

    int n = in_sizes[0] / DD;   // 100000
    int E = in_sizes[1] / 2;    // 1600000

    // Fork-join: GEMM branch concurrent with edge-CSR branch; join at k_fused.
    cudaStream_t s2;
    cudaEvent_t evFork, evJoin;
    cudaStreamCreateWithFlags(&s2, cudaStreamNonBlocking);
    cudaEventCreateWithFlags(&evFork, cudaEventDisableTiming);
    cudaEventCreateWithFlags(&evJoin, cudaEventDisableTiming);

    cudaEventRecord(evFork, 0);
    cudaStreamWaitEvent(s2, evFork, 0);
    k_prepw<<<32, 256, 0, s2>>>(Wl, Wr);
    k_tc   <<<(n + 63) / 64, 256, 0, s2>>>(x, n);
    cudaEventRecord(evJoin, s2);

    k_zero   <<<256, 256>>>((const int*)ei);
    k_hist   <<<2048, 256>>>(ei, E);
    k_scan1  <<<NBLK, 256>>>();
    k_scan2  <<<1, 512>>>(E);
    k_scan3  <<<256, 256>>>();
    k_scatter<<<2048, 256>>>(ei, E);

    cudaStreamWaitEvent(0, evJoin, 0);
    k_fused  <<<(n * 32 + 255) / 256, 256>>>(out, att, bias, n);
}

// round 13
// speedup vs baseline: 1.7675x; 1.1085x over previous
#include <cuda_runtime.h>
#include <cuda_bf16.h>
#include <cuda_fp16.h>

#define NN 100000
#define DD 128
#define EE 1600000
#define NBLK 391   // ceil(NN/256)

// ---- scratch (__device__ globals per allocation-free rule) ----
__device__ unsigned g_xlh[(size_t)NN * 64]; // xl as half2 pairs (25.6 MB, L2-resident)
__device__ float    g_xr[(size_t)NN * DD];  // x @ W_r (streamed once)
__device__ int      g_srcs[EE];
__device__ int      g_cnt[NN];
__device__ int      g_off[NN + 1];
__device__ int      g_cur[NN];
__device__ int      g_bsum[512];
__device__ int      g_is64;
// W pre-packed into bf16 mma-fragment layout: [ks(8)][j(32)][lane(32)][2] u32
__device__ unsigned g_wbh[16384];   // 64 KB hi component
__device__ unsigned g_wbl[16384];   // 64 KB lo component

__device__ __forceinline__ unsigned pkbf(float a, float b, float* ra, float* rb) {
    __nv_bfloat16 ha = __float2bfloat16(a), hb = __float2bfloat16(b);
    *ra = a - __bfloat162float(ha);
    *rb = b - __bfloat162float(hb);
    return (unsigned)__bfloat16_as_ushort(ha) |
           ((unsigned)__bfloat16_as_ushort(hb) << 16);
}
__device__ __forceinline__ unsigned pkbf2(float a, float b) {
    return (unsigned)__bfloat16_as_ushort(__float2bfloat16(a)) |
           ((unsigned)__bfloat16_as_ushort(__float2bfloat16(b)) << 16);
}
__device__ __forceinline__ void mma_bf16(float* c, const unsigned* a,
                                         unsigned b0, unsigned b1) {
    asm volatile(
        "mma.sync.aligned.m16n8k16.row.col.f32.bf16.bf16.f32 "
        "{%0,%1,%2,%3}, {%4,%5,%6,%7}, {%8,%9}, {%0,%1,%2,%3};"
        : "+f"(c[0]), "+f"(c[1]), "+f"(c[2]), "+f"(c[3])
        : "r"(a[0]), "r"(a[1]), "r"(a[2]), "r"(a[3]), "r"(b0), "r"(b1));
}

// ---------------------------------------------------------------------------
// K0: zero degree counters + detect edge dtype (int64 vs int32).
// ---------------------------------------------------------------------------
__global__ void k_zero(const int* __restrict__ ei_raw) {
    if (blockIdx.x == 0 && threadIdx.x == 0) {
        int all_zero = 1;
        for (int k = 0; k < 128; k++)
            if (ei_raw[2 * k + 1] != 0) { all_zero = 0; break; }
        g_is64 = all_zero;
    }
    for (int i = blockIdx.x * blockDim.x + threadIdx.x; i < NN;
         i += gridDim.x * blockDim.x)
        g_cnt[i] = 0;
}

__global__ void k_hist(const void* __restrict__ ei_raw, int E) {
    int is64 = g_is64;
    const long long* e64 = (const long long*)ei_raw;
    const int*       e32 = (const int*)ei_raw;
    for (int e = blockIdx.x * blockDim.x + threadIdx.x; e < E;
         e += gridDim.x * blockDim.x) {
        int d = is64 ? (int)__ldcs(&e64[E + e]) : __ldcs(&e32[E + e]);
        d = min(max(d, 0), NN - 1);
        atomicAdd(&g_cnt[d], 1);
    }
}

// ---------------------------------------------------------------------------
// pre-split + pre-pack W into per-lane bf16 fragment layout.
// ---------------------------------------------------------------------------
__global__ void k_prepw(const float* __restrict__ Wl,
                        const float* __restrict__ Wr) {
    int i = blockIdx.x * 256 + threadIdx.x;  // 8192 = 8ks * 32j * 32lane
    int lane = i & 31, j = (i >> 5) & 31, ks = i >> 10;
    int g = lane >> 2, t = lane & 3;
    int nc = j * 8 + g;
    const float* W = (nc < 128) ? Wl : Wr;
    int n = nc & 127;
    int k0 = ks * 16 + 2 * t;
    float w00 = W[(size_t)k0 * 128 + n];
    float w01 = W[(size_t)(k0 + 1) * 128 + n];
    float w10 = W[(size_t)(k0 + 8) * 128 + n];
    float w11 = W[(size_t)(k0 + 9) * 128 + n];
    float r0, r1, r2, r3;
    unsigned h0 = pkbf(w00, w01, &r0, &r1);
    unsigned h1 = pkbf(w10, w11, &r2, &r3);
    g_wbh[2 * i]     = h0;
    g_wbh[2 * i + 1] = h1;
    g_wbl[2 * i]     = pkbf2(r0, r1);
    g_wbl[2 * i + 1] = pkbf2(r2, r3);
}

// ---------------------------------------------------------------------------
// tensor dual GEMM via mma.sync bf16 m16n8k16, 3-way split (hi*hi+lo*hi+hi*lo).
// B fragments double-buffered (prefetch next (ks,jj) during current MMAs).
// ---------------------------------------------------------------------------
#define SA_STR 68   // u32 stride: banks (4g+t) all distinct -> conflict-free

__global__ __launch_bounds__(256, 2)
void k_tc(const float* __restrict__ x, int n) {
    __shared__ unsigned sAh[64 * SA_STR];
    __shared__ unsigned sAl[64 * SA_STR];

    int tid  = threadIdx.x;
    int lane = tid & 31;
    int wid  = tid >> 5;
    int row0  = blockIdx.x * 64;
    int mrow0 = (wid & 1) * 32;        // warp row offset
    int jbase = (wid >> 1) * 8;        // warp n-chunk base (0,8,16,24)

    // ---- stage whole A tile: 64 rows x 128 k -> bf16 hi/lo kpairs ----
    {
        int row = tid >> 2;            // 0..63
        int t4  = tid & 3;             // kpair range [16*t4, 16*t4+16)
        const float4* xr = (const float4*)(x + (size_t)(row0 + row) * 128 + t4 * 32);
        bool ok = (row0 + row) < n;
#pragma unroll
        for (int q = 0; q < 8; q++) {
            float4 f = ok ? __ldcs(&xr[q]) : make_float4(0.f, 0.f, 0.f, 0.f);
            float r0, r1, r2, r3;
            unsigned h0 = pkbf(f.x, f.y, &r0, &r1);
            unsigned h1 = pkbf(f.z, f.w, &r2, &r3);
            int kp = t4 * 16 + q * 2;
            sAh[row * SA_STR + kp]     = h0;
            sAh[row * SA_STR + kp + 1] = h1;
            sAl[row * SA_STR + kp]     = pkbf2(r0, r1);
            sAl[row * SA_STR + kp + 1] = pkbf2(r2, r3);
        }
    }
    __syncthreads();

    float acc[2][8][4] = {};
    int g = lane >> 2, t = lane & 3;

    // B-fragment double buffer: index q = ks*8 + jj
    uint2 bh = ((const uint2*)g_wbh)[(jbase) * 32 + lane];
    uint2 bl = ((const uint2*)g_wbl)[(jbase) * 32 + lane];

#pragma unroll
    for (int ks = 0; ks < 8; ks++) {
        unsigned ah[2][4], al[2][4];
#pragma unroll
        for (int m = 0; m < 2; m++) {
            int r = mrow0 + m * 16 + g;
            int kp = ks * 8 + t;
            ah[m][0] = sAh[r * SA_STR + kp];
            ah[m][1] = sAh[(r + 8) * SA_STR + kp];
            ah[m][2] = sAh[r * SA_STR + kp + 4];
            ah[m][3] = sAh[(r + 8) * SA_STR + kp + 4];
            al[m][0] = sAl[r * SA_STR + kp];
            al[m][1] = sAl[(r + 8) * SA_STR + kp];
            al[m][2] = sAl[r * SA_STR + kp + 4];
            al[m][3] = sAl[(r + 8) * SA_STR + kp + 4];
        }
#pragma unroll
        for (int jj = 0; jj < 8; jj++) {
            uint2 cbh = bh, cbl = bl;
            // prefetch next (ks,jj) fragment while MMAs run
            int qn = ks * 8 + jj + 1;
            if (qn < 64) {
                int ks2 = qn >> 3, jj2 = qn & 7;
                int fidx = (ks2 * 32 + jbase + jj2) * 32 + lane;
                bh = ((const uint2*)g_wbh)[fidx];
                bl = ((const uint2*)g_wbl)[fidx];
            }
#pragma unroll
            for (int m = 0; m < 2; m++) {
                mma_bf16(acc[m][jj], ah[m], cbh.x, cbh.y);
                mma_bf16(acc[m][jj], al[m], cbh.x, cbh.y);
                mma_bf16(acc[m][jj], ah[m], cbl.x, cbl.y);
            }
        }
    }

#pragma unroll
    for (int m = 0; m < 2; m++) {
        int row  = row0 + mrow0 + m * 16 + g;
        int row8 = row + 8;
#pragma unroll
        for (int jj = 0; jj < 8; jj++) {
            int col = (jbase + jj) * 8 + 2 * t;
            if (col < 128) {
                __half2 h01 = __floats2half2_rn(acc[m][jj][0], acc[m][jj][1]);
                __half2 h23 = __floats2half2_rn(acc[m][jj][2], acc[m][jj][3]);
                if (row < n)
                    g_xlh[(size_t)row * 64 + (col >> 1)] = *(unsigned*)&h01;
                if (row8 < n)
                    g_xlh[(size_t)row8 * 64 + (col >> 1)] = *(unsigned*)&h23;
            } else {
                int cc = col & 127;
                if (row < n)
                    *(float2*)(g_xr + (size_t)row * 128 + cc) =
                        make_float2(acc[m][jj][0], acc[m][jj][1]);
                if (row8 < n)
                    *(float2*)(g_xr + (size_t)row8 * 128 + cc) =
                        make_float2(acc[m][jj][2], acc[m][jj][3]);
            }
        }
    }
}

// ---- 2-level exclusive scan of g_cnt -> g_off ----
__global__ void k_scan1() {
    __shared__ int s[256];
    int t = threadIdx.x;
    int i = blockIdx.x * 256 + t;
    int v = (i < NN) ? g_cnt[i] : 0;
    s[t] = v;
    __syncthreads();
#pragma unroll
    for (int d = 1; d < 256; d <<= 1) {
        int add = (t >= d) ? s[t - d] : 0;
        __syncthreads();
        s[t] += add;
        __syncthreads();
    }
    if (i < NN) g_off[i] = s[t] - v;
    if (t == 255) g_bsum[blockIdx.x] = s[255];
}

__global__ void k_scan2(int E) {
    __shared__ int s[512];
    int t = threadIdx.x;
    int v = (t < NBLK) ? g_bsum[t] : 0;
    s[t] = v;
    __syncthreads();
#pragma unroll
    for (int d = 1; d < 512; d <<= 1) {
        int add = (t >= d) ? s[t - d] : 0;
        __syncthreads();
        s[t] += add;
        __syncthreads();
    }
    if (t < NBLK) g_bsum[t] = s[t] - v;
    if (t == 0) g_off[NN] = E;
}

__global__ void k_scan3() {
    for (int i = blockIdx.x * blockDim.x + threadIdx.x; i < NN;
         i += gridDim.x * blockDim.x) {
        int o = g_off[i] + g_bsum[i >> 8];
        g_off[i] = o;
        g_cur[i] = o;
    }
}

__global__ void k_scatter(const void* __restrict__ ei_raw, int E) {
    int is64 = g_is64;
    const long long* e64 = (const long long*)ei_raw;
    const int*       e32 = (const int*)ei_raw;
    for (int e = blockIdx.x * blockDim.x + threadIdx.x; e < E;
         e += gridDim.x * blockDim.x) {
        int s, d;
        if (is64) { s = (int)__ldcs(&e64[e]); d = (int)__ldcs(&e64[E + e]); }
        else      { s = __ldcs(&e32[e]);      d = __ldcs(&e32[E + e]); }
        s = min(max(s, 0), NN - 1);
        d = min(max(d, 0), NN - 1);
        int pos = atomicAdd(&g_cur[d], 1);
        __stcs(&g_srcs[pos], s);
    }
}

// ---------------------------------------------------------------------------
// fused score + softmax + aggregate: one warp per node, single pass.
// Butterfly (shfl_xor) reduction within 8-lane head groups -> all lanes hold
// the head sum; exp computed on all lanes (MUFU cost is per-instruction,
// identical to leader-only, but no divergent branch / broadcast shfl).
// ---------------------------------------------------------------------------
__global__ void k_fused(float* __restrict__ out,
                        const float* __restrict__ att,
                        const float* __restrict__ bias, int n) {
    int node = (blockIdx.x * blockDim.x + threadIdx.x) >> 5;
    int lane = threadIdx.x & 31;
    if (node >= n) return;

    float4 a4 = ((const float4*)att)[lane];
    float c1x = 0.6f * a4.x, c1y = 0.6f * a4.y, c1z = 0.6f * a4.z, c1w = 0.6f * a4.w;
    float c2x = 0.4f * a4.x, c2y = 0.4f * a4.y, c2z = 0.4f * a4.z, c2w = 0.4f * a4.w;

    float4 xi = __ldcs(&((const float4*)(g_xr + (size_t)node * 128))[lane]);
    int beg = g_off[node];
    int end = g_off[node + 1];

    float4 acc = make_float4(0.f, 0.f, 0.f, 0.f);
    float den = 0.f;

    int p = beg;
    for (; p + 3 < end; p += 4) {
        int  si[4];
        uint2 xu[4];
#pragma unroll
        for (int u = 0; u < 4; u++) si[u] = __ldcs(&g_srcs[p + u]);
#pragma unroll
        for (int u = 0; u < 4; u++)
            xu[u] = __ldg(&((const uint2*)g_xlh)[(size_t)si[u] * 32 + lane]);

        float4 xj[4];
        float sc[4];
#pragma unroll
        for (int u = 0; u < 4; u++) {
            float2 f01 = __half22float2(*(__half2*)&xu[u].x);
            float2 f23 = __half22float2(*(__half2*)&xu[u].y);
            xj[u] = make_float4(f01.x, f01.y, f23.x, f23.y);
            float v, s;
            v = xi.x + xj[u].x; s  = c1x * v; s = fmaf(c2x, fabsf(v), s);
            v = xi.y + xj[u].y; s = fmaf(c1y, v, s); s = fmaf(c2y, fabsf(v), s);
            v = xi.z + xj[u].z; s = fmaf(c1z, v, s); s = fmaf(c2z, fabsf(v), s);
            v = xi.w + xj[u].w; s = fmaf(c1w, v, s); s = fmaf(c2w, fabsf(v), s);
            sc[u] = s;
        }
#pragma unroll
        for (int u = 0; u < 4; u++) sc[u] += __shfl_xor_sync(0xffffffffu, sc[u], 1, 8);
#pragma unroll
        for (int u = 0; u < 4; u++) sc[u] += __shfl_xor_sync(0xffffffffu, sc[u], 2, 8);
#pragma unroll
        for (int u = 0; u < 4; u++) sc[u] += __shfl_xor_sync(0xffffffffu, sc[u], 4, 8);

        float ex[4];
#pragma unroll
        for (int u = 0; u < 4; u++) ex[u] = __expf(sc[u]);

#pragma unroll
        for (int u = 0; u < 4; u++) {
            den += ex[u];
            acc.x = fmaf(ex[u], xj[u].x, acc.x);
            acc.y = fmaf(ex[u], xj[u].y, acc.y);
            acc.z = fmaf(ex[u], xj[u].z, acc.z);
            acc.w = fmaf(ex[u], xj[u].w, acc.w);
        }
    }
    for (; p < end; p++) {
        int s0 = __ldcs(&g_srcs[p]);
        uint2 xu = __ldg(&((const uint2*)g_xlh)[(size_t)s0 * 32 + lane]);
        float2 f01 = __half22float2(*(__half2*)&xu.x);
        float2 f23 = __half22float2(*(__half2*)&xu.y);
        float4 xj0 = make_float4(f01.x, f01.y, f23.x, f23.y);
        float v, s;
        v = xi.x + xj0.x; s  = c1x * v; s = fmaf(c2x, fabsf(v), s);
        v = xi.y + xj0.y; s = fmaf(c1y, v, s); s = fmaf(c2y, fabsf(v), s);
        v = xi.z + xj0.z; s = fmaf(c1z, v, s); s = fmaf(c2z, fabsf(v), s);
        v = xi.w + xj0.w; s = fmaf(c1w, v, s); s = fmaf(c2w, fabsf(v), s);
        s += __shfl_xor_sync(0xffffffffu, s, 1, 8);
        s += __shfl_xor_sync(0xffffffffu, s, 2, 8);
        s += __shfl_xor_sync(0xffffffffu, s, 4, 8);
        float ex0 = __expf(s);
        den += ex0;
        acc.x = fmaf(ex0, xj0.x, acc.x);
        acc.y = fmaf(ex0, xj0.y, acc.y);
        acc.z = fmaf(ex0, xj0.z, acc.z);
        acc.w = fmaf(ex0, xj0.w, acc.w);
    }

    float invd = 1.f / (den + 1e-16f);
    float4 b4 = ((const float4*)bias)[lane];
    float4 o;
    o.x = fmaf(acc.x, invd, b4.x);
    o.y = fmaf(acc.y, invd, b4.y);
    o.z = fmaf(acc.z, invd, b4.z);
    o.w = fmaf(acc.w, invd, b4.w);
    __stcs(&((float4*)(out + (size_t)node * 128))[lane], o);
}

extern "C" void kernel_launch(void* const* d_in, const int* in_sizes, int n_in,
                              void* d_out, int out_size) {
    const float* x    = (const float*)d_in[0];
    const void*  ei   = d_in[1];
    const float* Wl   = (const float*)d_in[2];
    const float* Wr   = (const float*)d_in[3];
    const float* att  = (const float*)d_in[4];
    const float* bias = (const float*)d_in[5];
    float*       out  = (float*)d_out;

    int n = in_sizes[0] / DD;   // 100000
    int E = in_sizes[1] / 2;    // 1600000

    // Fork-join: GEMM branch concurrent with edge-CSR branch; join at k_fused.
    cudaStream_t s2;
    cudaEvent_t evFork, evJoin;
    cudaStreamCreateWithFlags(&s2, cudaStreamNonBlocking);
    cudaEventCreateWithFlags(&evFork, cudaEventDisableTiming);
    cudaEventCreateWithFlags(&evJoin, cudaEventDisableTiming);

    cudaEventRecord(evFork, 0);
    cudaStreamWaitEvent(s2, evFork, 0);
    k_prepw<<<32, 256, 0, s2>>>(Wl, Wr);
    k_tc   <<<(n + 63) / 64, 256, 0, s2>>>(x, n);
    cudaEventRecord(evJoin, s2);

    k_zero   <<<256, 256>>>((const int*)ei);
    k_hist   <<<2048, 256>>>(ei, E);
    k_scan1  <<<NBLK, 256>>>();
    k_scan2  <<<1, 512>>>(E);
    k_scan3  <<<256, 256>>>();
    k_scatter<<<2048, 256>>>(ei, E);

    cudaStreamWaitEvent(0, evJoin, 0);
    k_fused  <<<(n * 32 + 255) / 256, 256>>>(out, att, bias, n);
}